// round 1
// baseline (speedup 1.0000x reference)
#include <cuda_runtime.h>
#include <cstdint>

#define B_  2
#define T_  2048
#define C_  768
#define H_  12
#define D_  64
#define HD_ 768
#define W3_ 2304   // 3*HD

// Scratch (static device globals — no runtime allocation)
__device__ float g_qkv[(size_t)B_ * T_ * W3_];   // [B,T,2304]
__device__ float g_ff [(size_t)B_ * T_ * T_];    // S then FF in-place
__device__ float g_ffsum[B_ * T_];
__device__ float g_att[(size_t)B_ * T_ * HD_];   // attention output pre-proj

// ---------------------------------------------------------------------------
// Generic fp32 tiled GEMM with bias: C[M,N] = A[M,K] @ B[K,N] + bias[N]
// 64x64 tile, BK=16, 256 threads, 4x4 micro-tile. M%64==N%64==K%16==0 assumed.
// ---------------------------------------------------------------------------
__global__ __launch_bounds__(256) void sgemm_bias(
    const float* __restrict__ A, const float* __restrict__ Bm,
    const float* __restrict__ bias, float* __restrict__ Cm,
    int M, int N, int K)
{
    __shared__ float As[16][64];
    __shared__ float Bs[16][64];
    int tid = threadIdx.x;
    int tx = tid & 15, ty = tid >> 4;
    int row0 = blockIdx.y * 64, col0 = blockIdx.x * 64;
    int ar = tid >> 2;          // 0..63
    int ac = (tid & 3) * 4;     // 0,4,8,12
    int bk = tid >> 4;          // 0..15
    int bn = (tid & 15) * 4;    // 0..60

    float acc[4][4] = {};
    const float* Ap = A + (size_t)(row0 + ar) * K + ac;
    const float* Bp = Bm + (size_t)bk * N + col0 + bn;

    for (int k0 = 0; k0 < K; k0 += 16) {
        float4 a = *(const float4*)(Ap + k0);
        As[ac + 0][ar] = a.x; As[ac + 1][ar] = a.y;
        As[ac + 2][ar] = a.z; As[ac + 3][ar] = a.w;
        *(float4*)&Bs[bk][bn] = *(const float4*)(Bp + (size_t)k0 * N);
        __syncthreads();
#pragma unroll
        for (int kk = 0; kk < 16; kk++) {
            float av[4], bv[4];
            *(float4*)av = *(const float4*)&As[kk][ty * 4];
            *(float4*)bv = *(const float4*)&Bs[kk][tx * 4];
#pragma unroll
            for (int i = 0; i < 4; i++)
#pragma unroll
                for (int j = 0; j < 4; j++)
                    acc[i][j] = fmaf(av[i], bv[j], acc[i][j]);
        }
        __syncthreads();
    }
#pragma unroll
    for (int i = 0; i < 4; i++) {
        int r = row0 + ty * 4 + i;
        float4 o;
        o.x = acc[i][0] + bias[col0 + tx * 4 + 0];
        o.y = acc[i][1] + bias[col0 + tx * 4 + 1];
        o.z = acc[i][2] + bias[col0 + tx * 4 + 2];
        o.w = acc[i][3] + bias[col0 + tx * 4 + 3];
        *(float4*)&Cm[(size_t)r * N + col0 + tx * 4] = o;
    }
}

// ---------------------------------------------------------------------------
// Head-0 selection scores: S[b,t,s] = relu(q0[t]·k0[s] / 8) for 0<s<t else 0.
// Writes full T×T (zeros above/at diagonal and col 0) so cumsum is uniform.
// ---------------------------------------------------------------------------
__global__ __launch_bounds__(256) void scores_kernel(
    const float* __restrict__ qkv, float* __restrict__ S)
{
    int b = blockIdx.z, tb = blockIdx.y, sb = blockIdx.x;
    int t0 = tb * 64, s0 = sb * 64;
    int tid = threadIdx.x, tx = tid & 15, ty = tid >> 4;
    float* Sb = S + (size_t)b * T_ * T_;

    if (s0 >= t0 + 64) {   // strictly upper tile -> zeros
        float4 z = make_float4(0.f, 0.f, 0.f, 0.f);
#pragma unroll
        for (int i = 0; i < 4; i++)
            *(float4*)&Sb[(size_t)(t0 + ty * 4 + i) * T_ + s0 + tx * 4] = z;
        return;
    }

    __shared__ float Qs[64][68];
    __shared__ float Ks[64][68];
    const float* qb = qkv + ((size_t)b * T_ + t0) * W3_;         // q head 0
    const float* kb = qkv + ((size_t)b * T_ + s0) * W3_ + HD_;   // k head 0
    int lr = tid >> 4, lc = (tid & 15) * 4;
#pragma unroll
    for (int g = 0; g < 4; g++) {
        int r = lr + g * 16;
        *(float4*)&Qs[r][lc] = *(const float4*)&qb[(size_t)r * W3_ + lc];
        *(float4*)&Ks[r][lc] = *(const float4*)&kb[(size_t)r * W3_ + lc];
    }
    __syncthreads();

    float acc[4][4] = {};
#pragma unroll
    for (int dk = 0; dk < 16; dk++) {
        float4 qv[4], kv[4];
#pragma unroll
        for (int i = 0; i < 4; i++) qv[i] = *(const float4*)&Qs[ty * 4 + i][dk * 4];
#pragma unroll
        for (int j = 0; j < 4; j++) kv[j] = *(const float4*)&Ks[tx * 4 + j][dk * 4];
#pragma unroll
        for (int i = 0; i < 4; i++)
#pragma unroll
            for (int j = 0; j < 4; j++)
                acc[i][j] += qv[i].x * kv[j].x + qv[i].y * kv[j].y
                           + qv[i].z * kv[j].z + qv[i].w * kv[j].w;
    }
#pragma unroll
    for (int i = 0; i < 4; i++) {
        int t = t0 + ty * 4 + i;
        float out[4];
#pragma unroll
        for (int j = 0; j < 4; j++) {
            int s = s0 + tx * 4 + j;
            float v = acc[i][j] * 0.125f;
            out[j] = (s < t && s > 0) ? fmaxf(v, 0.f) : 0.f;
        }
        *(float4*)&Sb[(size_t)t * T_ + s0 + tx * 4] = *(float4*)out;
    }
}

// ---------------------------------------------------------------------------
// Exclusive cumsum down columns (axis t), in place: FF[t,s] = sum_{t'<t} S[t',s]
// ---------------------------------------------------------------------------
__global__ __launch_bounds__(256) void cumsum_kernel(float* __restrict__ FF)
{
    int b = blockIdx.y;
    int s = blockIdx.x * 256 + threadIdx.x;
    float* p = FF + (size_t)b * T_ * T_ + s;
    float acc = 0.f;
#pragma unroll 8
    for (int t = 0; t < T_; t++) {
        float v = p[(size_t)t * T_];
        p[(size_t)t * T_] = acc;
        acc += v;
    }
}

// ---------------------------------------------------------------------------
// FF_sum[b,t] = sum_s min(FF[b,t,s], 1)   (FF >= 0)
// ---------------------------------------------------------------------------
__global__ __launch_bounds__(256) void ffsum_kernel(const float* __restrict__ FF)
{
    int b = blockIdx.y, t = blockIdx.x;
    const float* row = FF + ((size_t)b * T_ + t) * T_;
    float s = 0.f;
    for (int j = threadIdx.x; j < T_; j += 256)
        s += fminf(row[j], 1.0f);
#pragma unroll
    for (int off = 16; off; off >>= 1) s += __shfl_xor_sync(0xffffffffu, s, off);
    __shared__ float red[32];
    int lane = threadIdx.x & 31, w = threadIdx.x >> 5;
    if (lane == 0) red[w] = s;
    __syncthreads();
    if (w == 0) {
        s = (lane < 8) ? red[lane] : 0.f;
#pragma unroll
        for (int off = 4; off; off >>= 1) s += __shfl_xor_sync(0xffffffffu, s, off);
        if (lane == 0) g_ffsum[b * T_ + t] = s;
    }
}

// M[0,b,i,j] = i - FF_sum[b,j]
__global__ __launch_bounds__(256) void m_kernel(float* __restrict__ Mout)
{
    size_t idx = (size_t)blockIdx.x * 256 + threadIdx.x;
    int j = (int)(idx % T_);
    size_t r = idx / T_;
    int i = (int)(r % T_);
    int b = (int)(r / T_);
    Mout[idx] = (float)i - g_ffsum[b * T_ + j];
}

// ---------------------------------------------------------------------------
// Causal flash attention with memory penalty:
//  logit(t,s) = q·k/8 - FF[b,t,s] for s<=t; softmax; O = P@V.
// One block per (64 q-rows, b*H+h). 256 threads, 4x4 tiles, fp32.
// ---------------------------------------------------------------------------
__global__ __launch_bounds__(256) void flash_kernel(
    const float* __restrict__ qkv, const float* __restrict__ FF,
    float* __restrict__ Y)
{
    extern __shared__ float sm[];
    float* Qs = sm;                  // [64][68]
    float* Ks = sm + 64 * 68;
    float* Vs = sm + 2 * 64 * 68;
    float* Ps = sm + 3 * 64 * 68;

    int tb = blockIdx.x;
    int bh = blockIdx.y;
    int b = bh / H_, h = bh % H_;
    int t0 = tb * 64;
    int tid = threadIdx.x, tx = tid & 15, ty = tid >> 4;
    int lr = tid >> 4, lc = (tid & 15) * 4;

    const float* qb = qkv + ((size_t)b * T_ + t0) * W3_ + h * D_;
#pragma unroll
    for (int g = 0; g < 4; g++) {
        int r = lr + g * 16;
        *(float4*)&Qs[r * 68 + lc] = *(const float4*)&qb[(size_t)r * W3_ + lc];
    }

    float m[4], l[4], o[4][4];
#pragma unroll
    for (int i = 0; i < 4; i++) {
        m[i] = -1e30f; l[i] = 0.f;
#pragma unroll
        for (int j = 0; j < 4; j++) o[i][j] = 0.f;
    }

    const float* ffb = FF + (size_t)b * T_ * T_;
    const float* kvb = qkv + (size_t)b * T_ * W3_;

    for (int kb = 0; kb <= tb; kb++) {
        int s0 = kb * 64;
        __syncthreads();   // prior-iter Ps/Vs reads done before reload
        const float* kp = kvb + (size_t)s0 * W3_ + HD_     + h * D_;
        const float* vp = kvb + (size_t)s0 * W3_ + 2 * HD_ + h * D_;
#pragma unroll
        for (int g = 0; g < 4; g++) {
            int r = lr + g * 16;
            *(float4*)&Ks[r * 68 + lc] = *(const float4*)&kp[(size_t)r * W3_ + lc];
            *(float4*)&Vs[r * 68 + lc] = *(const float4*)&vp[(size_t)r * W3_ + lc];
        }
        __syncthreads();

        float acc[4][4] = {};
#pragma unroll
        for (int dk = 0; dk < 16; dk++) {
            float4 qv[4], kv4[4];
#pragma unroll
            for (int i = 0; i < 4; i++) qv[i]  = *(const float4*)&Qs[(ty * 4 + i) * 68 + dk * 4];
#pragma unroll
            for (int j = 0; j < 4; j++) kv4[j] = *(const float4*)&Ks[(tx * 4 + j) * 68 + dk * 4];
#pragma unroll
            for (int i = 0; i < 4; i++)
#pragma unroll
                for (int j = 0; j < 4; j++)
                    acc[i][j] += qv[i].x * kv4[j].x + qv[i].y * kv4[j].y
                               + qv[i].z * kv4[j].z + qv[i].w * kv4[j].w;
        }

        bool diag = (kb == tb);
#pragma unroll
        for (int i = 0; i < 4; i++) {
            int t = t0 + ty * 4 + i;
            float4 ff4 = *(const float4*)&ffb[(size_t)t * T_ + s0 + tx * 4];
            float pr[4];
            pr[0] = acc[i][0] * 0.125f - ff4.x;
            pr[1] = acc[i][1] * 0.125f - ff4.y;
            pr[2] = acc[i][2] * 0.125f - ff4.z;
            pr[3] = acc[i][3] * 0.125f - ff4.w;
            if (diag) {
#pragma unroll
                for (int j = 0; j < 4; j++)
                    if (s0 + tx * 4 + j > t) pr[j] = -1e30f;
            }
            float rm = fmaxf(fmaxf(pr[0], pr[1]), fmaxf(pr[2], pr[3]));
#pragma unroll
            for (int off = 1; off < 16; off <<= 1)
                rm = fmaxf(rm, __shfl_xor_sync(0xffffffffu, rm, off));
            float mn = fmaxf(m[i], rm);
            float corr = __expf(m[i] - mn);
            m[i] = mn;
            float ps = 0.f;
#pragma unroll
            for (int j = 0; j < 4; j++) {
                float p = __expf(pr[j] - mn);
                pr[j] = p; ps += p;
            }
#pragma unroll
            for (int off = 1; off < 16; off <<= 1)
                ps += __shfl_xor_sync(0xffffffffu, ps, off);
            l[i] = l[i] * corr + ps;
#pragma unroll
            for (int j = 0; j < 4; j++) o[i][j] *= corr;
            *(float4*)&Ps[(ty * 4 + i) * 68 + tx * 4] = *(float4*)pr;
        }
        __syncthreads();

#pragma unroll 4
        for (int ss = 0; ss < 64; ss++) {
            float4 v4 = *(const float4*)&Vs[ss * 68 + tx * 4];
#pragma unroll
            for (int i = 0; i < 4; i++) {
                float p = Ps[(ty * 4 + i) * 68 + ss];
                o[i][0] = fmaf(p, v4.x, o[i][0]);
                o[i][1] = fmaf(p, v4.y, o[i][1]);
                o[i][2] = fmaf(p, v4.z, o[i][2]);
                o[i][3] = fmaf(p, v4.w, o[i][3]);
            }
        }
    }

    float* yb = Y + ((size_t)b * T_ + t0) * HD_ + h * D_;
#pragma unroll
    for (int i = 0; i < 4; i++) {
        float inv = 1.f / l[i];
        float4 w = make_float4(o[i][0] * inv, o[i][1] * inv,
                               o[i][2] * inv, o[i][3] * inv);
        *(float4*)&yb[(size_t)(ty * 4 + i) * HD_ + tx * 4] = w;
    }
}

// ---------------------------------------------------------------------------
extern "C" void kernel_launch(void* const* d_in, const int* in_sizes, int n_in,
                              void* d_out, int out_size)
{
    const float* x      = (const float*)d_in[0];
    const float* W_attn = (const float*)d_in[1];
    const float* b_attn = (const float*)d_in[2];
    const float* W_proj = (const float*)d_in[3];
    const float* b_proj = (const float*)d_in[4];

    float* out  = (float*)d_out;
    float* y_out = out;                                   // [B,T,C]
    float* m_out = out + (size_t)B_ * T_ * C_;            // [1,B,T,T]

    float *qkv, *ff, *att;
    cudaGetSymbolAddress((void**)&qkv, g_qkv);
    cudaGetSymbolAddress((void**)&ff,  g_ff);
    cudaGetSymbolAddress((void**)&att, g_att);

    dim3 blk(256);

    // 1) QKV GEMM
    sgemm_bias<<<dim3(W3_ / 64, (B_ * T_) / 64), blk>>>(
        x, W_attn, b_attn, qkv, B_ * T_, W3_, C_);

    // 2) head-0 scores S
    scores_kernel<<<dim3(T_ / 64, T_ / 64, B_), blk>>>(qkv, ff);

    // 3) exclusive cumsum -> FF (in place)
    cumsum_kernel<<<dim3(T_ / 256, B_), blk>>>(ff);

    // 4) FF_sum rows
    ffsum_kernel<<<dim3(T_, B_), blk>>>(ff);

    // 5) M output
    m_kernel<<<dim3((unsigned)(((size_t)B_ * T_ * T_) / 256)), blk>>>(m_out);

    // 6) flash attention with penalty
    int smem = 4 * 64 * 68 * (int)sizeof(float);   // 69632 B
    cudaFuncSetAttribute(flash_kernel,
                         cudaFuncAttributeMaxDynamicSharedMemorySize, smem);
    flash_kernel<<<dim3(T_ / 64, B_ * H_), blk, smem>>>(qkv, ff, att);

    // 7) output projection
    sgemm_bias<<<dim3(C_ / 64, (B_ * T_) / 64), blk>>>(
        att, W_proj, b_proj, y_out, B_ * T_, C_, HD_);
}

// round 2
// speedup vs baseline: 1.5430x; 1.5430x over previous
#include <cuda_runtime.h>
#include <cstdint>

#define B_  2
#define T_  2048
#define C_  768
#define H_  12
#define D_  64
#define HD_ 768
#define W3_ 2304   // 3*HD
#define CH_ 8
#define CL_ (T_/CH_)   // 256

typedef unsigned long long u64;

// ---- packed f32x2 helpers -------------------------------------------------
__device__ __forceinline__ u64 pk2(float lo, float hi) {
    u64 r; asm("mov.b64 %0,{%1,%2};" : "=l"(r) : "f"(lo), "f"(hi)); return r;
}
__device__ __forceinline__ u64 dup2(float v) { return pk2(v, v); }
__device__ __forceinline__ float2 up2(u64 v) {
    float2 r; asm("mov.b64 {%0,%1},%2;" : "=f"(r.x), "=f"(r.y) : "l"(v)); return r;
}
__device__ __forceinline__ void fma2(u64& d, u64 a, u64 b) {
    asm("fma.rn.f32x2 %0,%1,%2,%3;" : "=l"(d) : "l"(a), "l"(b), "l"(d));
}
__device__ __forceinline__ u64 mul2(u64 a, u64 b) {
    u64 d; asm("mul.rn.f32x2 %0,%1,%2;" : "=l"(d) : "l"(a), "l"(b)); return d;
}

// Scratch (static device globals — no runtime allocation)
__device__ float g_qkv[(size_t)B_ * T_ * W3_];   // [B,T,2304]
__device__ float g_ff [(size_t)B_ * T_ * T_];    // S then FF in-place
__device__ float g_ffsum[B_ * T_];
__device__ float g_att[(size_t)B_ * T_ * HD_];   // attention output pre-proj
__device__ float g_csum[B_ * CH_ * T_];          // chunk sums for 2-pass scan

// ---------------------------------------------------------------------------
// fp32 GEMM with bias using packed f32x2 FMA.
// Tile 128(M) x 128(N), BK=16, 256 threads, 8x8 micro-tile (two 4-groups).
// ---------------------------------------------------------------------------
__global__ __launch_bounds__(256) void sgemm_f2(
    const float* __restrict__ A, const float* __restrict__ Bm,
    const float* __restrict__ bias, float* __restrict__ Cm,
    int M, int N, int K)
{
    __shared__ float As[16][132];   // [k][m] transposed
    __shared__ float Bs[16][132];   // [k][n]
    int tid = threadIdx.x;
    int tx = tid & 15, ty = tid >> 4;
    int row0 = blockIdx.y * 128, col0 = blockIdx.x * 128;

    int arow  = tid >> 1;
    int akoff = (tid & 1) * 8;
    int bkb   = tid >> 4;
    int bcol  = (tid & 15) * 8;

    const float* Ap = A + (size_t)(row0 + arow) * K + akoff;
    const float* Bp = Bm + (size_t)bkb * N + col0 + bcol;

    u64 acc[8][4];
#pragma unroll
    for (int i = 0; i < 8; i++)
#pragma unroll
        for (int j = 0; j < 4; j++) acc[i][j] = 0ull;

    for (int k0 = 0; k0 < K; k0 += 16) {
        float4 a0 = *(const float4*)(Ap + k0);
        float4 a1 = *(const float4*)(Ap + k0 + 4);
        float4 b0 = *(const float4*)(Bp + (size_t)k0 * N);
        float4 b1 = *(const float4*)(Bp + (size_t)k0 * N + 4);
        __syncthreads();
        As[akoff + 0][arow] = a0.x; As[akoff + 1][arow] = a0.y;
        As[akoff + 2][arow] = a0.z; As[akoff + 3][arow] = a0.w;
        As[akoff + 4][arow] = a1.x; As[akoff + 5][arow] = a1.y;
        As[akoff + 6][arow] = a1.z; As[akoff + 7][arow] = a1.w;
        *(float4*)&Bs[bkb][bcol]     = b0;
        *(float4*)&Bs[bkb][bcol + 4] = b1;
        __syncthreads();
#pragma unroll
        for (int kk = 0; kk < 16; kk++) {
            float4 av0 = *(const float4*)&As[kk][ty * 4];
            float4 av1 = *(const float4*)&As[kk][64 + ty * 4];
            u64 ad[8];
            ad[0] = dup2(av0.x); ad[1] = dup2(av0.y);
            ad[2] = dup2(av0.z); ad[3] = dup2(av0.w);
            ad[4] = dup2(av1.x); ad[5] = dup2(av1.y);
            ad[6] = dup2(av1.z); ad[7] = dup2(av1.w);
            u64 bx[4];
            bx[0] = *(const u64*)&Bs[kk][tx * 4];
            bx[1] = *(const u64*)&Bs[kk][tx * 4 + 2];
            bx[2] = *(const u64*)&Bs[kk][64 + tx * 4];
            bx[3] = *(const u64*)&Bs[kk][64 + tx * 4 + 2];
#pragma unroll
            for (int i = 0; i < 8; i++)
#pragma unroll
                for (int j = 0; j < 4; j++)
                    fma2(acc[i][j], ad[i], bx[j]);
        }
    }

#pragma unroll
    for (int i = 0; i < 8; i++) {
        int r = row0 + ((i < 4) ? (ty * 4 + i) : (64 + ty * 4 + (i - 4)));
#pragma unroll
        for (int g = 0; g < 2; g++) {
            int c = col0 + g * 64 + tx * 4;
            float2 p0 = up2(acc[i][g * 2 + 0]);
            float2 p1 = up2(acc[i][g * 2 + 1]);
            float4 o;
            o.x = p0.x + bias[c + 0];
            o.y = p0.y + bias[c + 1];
            o.z = p1.x + bias[c + 2];
            o.w = p1.y + bias[c + 3];
            *(float4*)&Cm[(size_t)r * N + c] = o;
        }
    }
}

// ---------------------------------------------------------------------------
// Head-0 selection scores: S[b,t,s] = relu(q0[t]·k0[s] / 8) for 0<s<t else 0.
// ---------------------------------------------------------------------------
__global__ __launch_bounds__(256) void scores_kernel(
    const float* __restrict__ qkv, float* __restrict__ S)
{
    int b = blockIdx.z, tb = blockIdx.y, sb = blockIdx.x;
    int t0 = tb * 64, s0 = sb * 64;
    int tid = threadIdx.x, tx = tid & 15, ty = tid >> 4;
    float* Sb = S + (size_t)b * T_ * T_;

    if (s0 >= t0 + 64) {   // strictly upper tile -> zeros
        float4 z = make_float4(0.f, 0.f, 0.f, 0.f);
#pragma unroll
        for (int i = 0; i < 4; i++)
            *(float4*)&Sb[(size_t)(t0 + ty * 4 + i) * T_ + s0 + tx * 4] = z;
        return;
    }

    __shared__ float Qs[64][68];
    __shared__ float Ks[64][68];
    const float* qb = qkv + ((size_t)b * T_ + t0) * W3_;         // q head 0
    const float* kb = qkv + ((size_t)b * T_ + s0) * W3_ + HD_;   // k head 0
    int lr = tid >> 4, lc = (tid & 15) * 4;
#pragma unroll
    for (int g = 0; g < 4; g++) {
        int r = lr + g * 16;
        *(float4*)&Qs[r][lc] = *(const float4*)&qb[(size_t)r * W3_ + lc];
        *(float4*)&Ks[r][lc] = *(const float4*)&kb[(size_t)r * W3_ + lc];
    }
    __syncthreads();

    float acc[4][4] = {};
#pragma unroll
    for (int dk = 0; dk < 16; dk++) {
        float4 qv[4], kv[4];
#pragma unroll
        for (int i = 0; i < 4; i++) qv[i] = *(const float4*)&Qs[ty * 4 + i][dk * 4];
#pragma unroll
        for (int j = 0; j < 4; j++) kv[j] = *(const float4*)&Ks[tx * 4 + j][dk * 4];
#pragma unroll
        for (int i = 0; i < 4; i++)
#pragma unroll
            for (int j = 0; j < 4; j++)
                acc[i][j] += qv[i].x * kv[j].x + qv[i].y * kv[j].y
                           + qv[i].z * kv[j].z + qv[i].w * kv[j].w;
    }
#pragma unroll
    for (int i = 0; i < 4; i++) {
        int t = t0 + ty * 4 + i;
        float out[4];
#pragma unroll
        for (int j = 0; j < 4; j++) {
            int s = s0 + tx * 4 + j;
            float v = acc[i][j] * 0.125f;
            out[j] = (s < t && s > 0) ? fmaxf(v, 0.f) : 0.f;
        }
        *(float4*)&Sb[(size_t)t * T_ + s0 + tx * 4] = *(float4*)out;
    }
}

// ---------------------------------------------------------------------------
// Two-pass exclusive column cumsum (axis t), in place.
// ---------------------------------------------------------------------------
__global__ __launch_bounds__(256) void cumsum_pass1(const float* __restrict__ S)
{
    int b = blockIdx.y;
    int chunk = blockIdx.z;
    int s = blockIdx.x * 256 + threadIdx.x;
    const float* p = S + (size_t)b * T_ * T_ + (size_t)chunk * CL_ * T_ + s;
    float acc = 0.f;
#pragma unroll 8
    for (int t = 0; t < CL_; t++) acc += p[(size_t)t * T_];
    g_csum[(b * CH_ + chunk) * T_ + s] = acc;
}

__global__ __launch_bounds__(256) void cumsum_pass2(float* __restrict__ S)
{
    int b = blockIdx.y;
    int chunk = blockIdx.z;
    int s = blockIdx.x * 256 + threadIdx.x;
    float base = 0.f;
    for (int c = 0; c < chunk; c++) base += g_csum[(b * CH_ + c) * T_ + s];
    float* p = S + (size_t)b * T_ * T_ + (size_t)chunk * CL_ * T_ + s;
    float acc = base;
#pragma unroll 8
    for (int t = 0; t < CL_; t++) {
        float v = p[(size_t)t * T_];
        p[(size_t)t * T_] = acc;
        acc += v;
    }
}

// ---------------------------------------------------------------------------
// FF_sum[b,t] = sum_s min(FF[b,t,s], 1)
// ---------------------------------------------------------------------------
__global__ __launch_bounds__(256) void ffsum_kernel(const float* __restrict__ FF)
{
    int b = blockIdx.y, t = blockIdx.x;
    const float4* row = (const float4*)(FF + ((size_t)b * T_ + t) * T_);
    float s = 0.f;
    for (int j = threadIdx.x; j < T_ / 4; j += 256) {
        float4 v = row[j];
        s += fminf(v.x, 1.f) + fminf(v.y, 1.f) + fminf(v.z, 1.f) + fminf(v.w, 1.f);
    }
#pragma unroll
    for (int off = 16; off; off >>= 1) s += __shfl_xor_sync(0xffffffffu, s, off);
    __shared__ float red[8];
    int lane = threadIdx.x & 31, w = threadIdx.x >> 5;
    if (lane == 0) red[w] = s;
    __syncthreads();
    if (w == 0) {
        s = (lane < 8) ? red[lane] : 0.f;
#pragma unroll
        for (int off = 4; off; off >>= 1) s += __shfl_xor_sync(0xffffffffu, s, off);
        if (lane == 0) g_ffsum[b * T_ + t] = s;
    }
}

// M[0,b,i,j] = i - FF_sum[b,j]  (float4 per thread)
__global__ __launch_bounds__(256) void m_kernel(float* __restrict__ Mout)
{
    size_t idx4 = (size_t)blockIdx.x * 256 + threadIdx.x;
    size_t idx = idx4 * 4;
    int j = (int)(idx % T_);
    size_t r = idx / T_;
    int i = (int)(r % T_);
    int b = (int)(r / T_);
    float4 fs = *(const float4*)&g_ffsum[b * T_ + j];
    float fi = (float)i;
    float4 o = make_float4(fi - fs.x, fi - fs.y, fi - fs.z, fi - fs.w);
    *(float4*)&Mout[idx] = o;
}

// ---------------------------------------------------------------------------
// Causal flash attention with memory penalty, packed f32x2.
// Block: 128 q-rows x full head; s-tiles of 128. 256 threads.
// Micro: 8 q-rows x 8 s-cols (QK) / 8 q-rows x 4 d-cols (PV).
// ---------------------------------------------------------------------------
__global__ __launch_bounds__(256) void flash_f2(
    const float* __restrict__ qkv, const float* __restrict__ FF,
    float* __restrict__ Y)
{
    extern __shared__ float sm[];
    float* Qs = sm;                       // [128][68]  row-major (t, d)
    float* Kt = sm + 128 * 68;            // [64][132]  transposed (d, s)
    float* Vs = Kt + 64 * 132;            // [128][68]  row-major (s, d)
    float* Ps = Vs + 128 * 68;            // [128][132] row-major (t, s)

    int tb = gridDim.x - 1 - blockIdx.x;  // big blocks first
    int bh = blockIdx.y;
    int b = bh / H_, h = bh % H_;
    int t0 = tb * 128;
    int tid = threadIdx.x, tx = tid & 15, ty = tid >> 4;

    // Load Q tile (128 x 64)
    {
        int tok = tid >> 1, dh = (tid & 1) * 32;
        const float* qp = qkv + ((size_t)(b * T_ + t0 + tok)) * W3_ + h * D_ + dh;
#pragma unroll
        for (int u = 0; u < 8; u++)
            *(float4*)&Qs[tok * 68 + dh + u * 4] = *(const float4*)(qp + u * 4);
    }

    float m[8], l[8];
    u64 o[8][2];
#pragma unroll
    for (int i = 0; i < 8; i++) {
        m[i] = -1e30f; l[i] = 0.f; o[i][0] = 0ull; o[i][1] = 0ull;
    }

    const float* ffb = FF + (size_t)b * T_ * T_;
    const float* kvb = qkv + (size_t)b * T_ * W3_;

    int tr[8];
#pragma unroll
    for (int i = 0; i < 8; i++)
        tr[i] = (i < 4) ? (ty * 4 + i) : (64 + ty * 4 + (i - 4));

    for (int kb = 0; kb <= tb; kb++) {
        int s0 = kb * 128;
        __syncthreads();
        // Load K transposed + V row-major
        {
            int tok = tid >> 1, dh = (tid & 1) * 32;
            const float* kp = kvb + (size_t)(s0 + tok) * W3_ + HD_     + h * D_ + dh;
            const float* vp = kvb + (size_t)(s0 + tok) * W3_ + 2 * HD_ + h * D_ + dh;
#pragma unroll
            for (int u = 0; u < 8; u++) {
                float4 kv = *(const float4*)(kp + u * 4);
                Kt[(dh + u * 4 + 0) * 132 + tok] = kv.x;
                Kt[(dh + u * 4 + 1) * 132 + tok] = kv.y;
                Kt[(dh + u * 4 + 2) * 132 + tok] = kv.z;
                Kt[(dh + u * 4 + 3) * 132 + tok] = kv.w;
                *(float4*)&Vs[tok * 68 + dh + u * 4] = *(const float4*)(vp + u * 4);
            }
        }
        __syncthreads();

        // QK^T: acc[8 rows][4 s-pairs]
        u64 acc[8][4];
#pragma unroll
        for (int i = 0; i < 8; i++)
#pragma unroll
            for (int j = 0; j < 4; j++) acc[i][j] = 0ull;

        for (int d = 0; d < 64; d++) {
            u64 kx[4];
            kx[0] = *(const u64*)&Kt[d * 132 + tx * 4];
            kx[1] = *(const u64*)&Kt[d * 132 + tx * 4 + 2];
            kx[2] = *(const u64*)&Kt[d * 132 + 64 + tx * 4];
            kx[3] = *(const u64*)&Kt[d * 132 + 64 + tx * 4 + 2];
#pragma unroll
            for (int i = 0; i < 8; i++) {
                u64 q = dup2(Qs[tr[i] * 68 + d]);
                fma2(acc[i][0], q, kx[0]);
                fma2(acc[i][1], q, kx[1]);
                fma2(acc[i][2], q, kx[2]);
                fma2(acc[i][3], q, kx[3]);
            }
        }

        bool diag = (kb == tb);
#pragma unroll
        for (int i = 0; i < 8; i++) {
            int t = t0 + tr[i];
            const float* ffr = ffb + (size_t)t * T_ + s0;
            float4 f0 = *(const float4*)(ffr + tx * 4);
            float4 f1 = *(const float4*)(ffr + 64 + tx * 4);
            float2 a01 = up2(acc[i][0]);
            float2 a23 = up2(acc[i][1]);
            float2 a45 = up2(acc[i][2]);
            float2 a67 = up2(acc[i][3]);
            float pr[8];
            pr[0] = a01.x * 0.125f - f0.x;
            pr[1] = a01.y * 0.125f - f0.y;
            pr[2] = a23.x * 0.125f - f0.z;
            pr[3] = a23.y * 0.125f - f0.w;
            pr[4] = a45.x * 0.125f - f1.x;
            pr[5] = a45.y * 0.125f - f1.y;
            pr[6] = a67.x * 0.125f - f1.z;
            pr[7] = a67.y * 0.125f - f1.w;
            if (diag) {
                int sb0 = s0 + tx * 4;
#pragma unroll
                for (int j = 0; j < 4; j++) {
                    if (sb0 + j > t)      pr[j]     = -1e30f;
                    if (sb0 + 64 + j > t) pr[4 + j] = -1e30f;
                }
            }
            float rm = fmaxf(fmaxf(fmaxf(pr[0], pr[1]), fmaxf(pr[2], pr[3])),
                             fmaxf(fmaxf(pr[4], pr[5]), fmaxf(pr[6], pr[7])));
#pragma unroll
            for (int off = 1; off < 16; off <<= 1)
                rm = fmaxf(rm, __shfl_xor_sync(0xffffffffu, rm, off));
            float mn = fmaxf(m[i], rm);
            float corr = __expf(m[i] - mn);
            m[i] = mn;
            float ps = 0.f;
#pragma unroll
            for (int j = 0; j < 8; j++) {
                float p = __expf(pr[j] - mn);
                pr[j] = p; ps += p;
            }
#pragma unroll
            for (int off = 1; off < 16; off <<= 1)
                ps += __shfl_xor_sync(0xffffffffu, ps, off);
            l[i] = l[i] * corr + ps;
            u64 c2 = dup2(corr);
            o[i][0] = mul2(o[i][0], c2);
            o[i][1] = mul2(o[i][1], c2);
            *(u64*)&Ps[tr[i] * 132 + tx * 4]          = pk2(pr[0], pr[1]);
            *(u64*)&Ps[tr[i] * 132 + tx * 4 + 2]      = pk2(pr[2], pr[3]);
            *(u64*)&Ps[tr[i] * 132 + 64 + tx * 4]     = pk2(pr[4], pr[5]);
            *(u64*)&Ps[tr[i] * 132 + 64 + tx * 4 + 2] = pk2(pr[6], pr[7]);
        }
        __syncthreads();

        // PV: o[8][2 pairs of d-cols]
#pragma unroll 4
        for (int ss = 0; ss < 128; ss++) {
            u64 v0 = *(const u64*)&Vs[ss * 68 + tx * 4];
            u64 v1 = *(const u64*)&Vs[ss * 68 + tx * 4 + 2];
#pragma unroll
            for (int i = 0; i < 8; i++) {
                u64 p = dup2(Ps[tr[i] * 132 + ss]);
                fma2(o[i][0], p, v0);
                fma2(o[i][1], p, v1);
            }
        }
    }

#pragma unroll
    for (int i = 0; i < 8; i++) {
        float inv = 1.f / l[i];
        float2 p0 = up2(o[i][0]);
        float2 p1 = up2(o[i][1]);
        float4 w = make_float4(p0.x * inv, p0.y * inv, p1.x * inv, p1.y * inv);
        *(float4*)&Y[((size_t)(b * T_ + t0 + tr[i])) * HD_ + h * D_ + tx * 4] = w;
    }
}

// ---------------------------------------------------------------------------
extern "C" void kernel_launch(void* const* d_in, const int* in_sizes, int n_in,
                              void* d_out, int out_size)
{
    const float* x      = (const float*)d_in[0];
    const float* W_attn = (const float*)d_in[1];
    const float* b_attn = (const float*)d_in[2];
    const float* W_proj = (const float*)d_in[3];
    const float* b_proj = (const float*)d_in[4];

    float* out   = (float*)d_out;
    float* y_out = out;                                   // [B,T,C]
    float* m_out = out + (size_t)B_ * T_ * C_;            // [1,B,T,T]

    float *qkv, *ff, *att;
    cudaGetSymbolAddress((void**)&qkv, g_qkv);
    cudaGetSymbolAddress((void**)&ff,  g_ff);
    cudaGetSymbolAddress((void**)&att, g_att);

    dim3 blk(256);

    // 1) QKV GEMM
    sgemm_f2<<<dim3(W3_ / 128, (B_ * T_) / 128), blk>>>(
        x, W_attn, b_attn, qkv, B_ * T_, W3_, C_);

    // 2) head-0 scores S
    scores_kernel<<<dim3(T_ / 64, T_ / 64, B_), blk>>>(qkv, ff);

    // 3) exclusive column cumsum, 2-pass
    cumsum_pass1<<<dim3(T_ / 256, B_, CH_), blk>>>(ff);
    cumsum_pass2<<<dim3(T_ / 256, B_, CH_), blk>>>(ff);

    // 4) FF_sum rows
    ffsum_kernel<<<dim3(T_, B_), blk>>>(ff);

    // 5) M output
    m_kernel<<<dim3((unsigned)(((size_t)B_ * T_ * T_) / 1024)), blk>>>(m_out);

    // 6) flash attention with penalty (128-row q blocks)
    int smem = (128 * 68 + 64 * 132 + 128 * 68 + 128 * 132) * (int)sizeof(float);
    cudaFuncSetAttribute(flash_f2,
                         cudaFuncAttributeMaxDynamicSharedMemorySize, smem);
    flash_f2<<<dim3(T_ / 128, B_ * H_), blk, smem>>>(qkv, ff, att);

    // 7) output projection
    sgemm_f2<<<dim3(C_ / 128, (B_ * T_) / 128), blk>>>(
        att, W_proj, b_proj, y_out, B_ * T_, C_, HD_);
}

// round 4
// speedup vs baseline: 1.9632x; 1.2723x over previous
#include <cuda_runtime.h>
#include <cuda_bf16.h>
#include <cstdint>

#define B_  2
#define T_  2048
#define C_  768
#define H_  12
#define D_  64
#define HD_ 768
#define W3_ 2304   // 3*HD
#define CH_ 32
#define CL_ (T_/CH_)   // 64

typedef unsigned long long u64;

// ---- packed f32x2 helpers -------------------------------------------------
__device__ __forceinline__ u64 pk2(float lo, float hi) {
    u64 r; asm("mov.b64 %0,{%1,%2};" : "=l"(r) : "f"(lo), "f"(hi)); return r;
}
__device__ __forceinline__ u64 dup2(float v) { return pk2(v, v); }
__device__ __forceinline__ float2 up2(u64 v) {
    float2 r; asm("mov.b64 {%0,%1},%2;" : "=f"(r.x), "=f"(r.y) : "l"(v)); return r;
}
__device__ __forceinline__ void fma2(u64& d, u64 a, u64 b) {
    asm("fma.rn.f32x2 %0,%1,%2,%3;" : "=l"(d) : "l"(a), "l"(b), "l"(d));
}

// ---- tf32 helpers -----------------------------------------------------------
__device__ __forceinline__ uint32_t tf32r(float x) {
    uint32_t r; asm("cvt.rna.tf32.f32 %0,%1;" : "=r"(r) : "f"(x)); return r;
}
#define MMA_TF32(c,a,b0,b1) \
    asm volatile("mma.sync.aligned.m16n8k8.row.col.f32.tf32.tf32.f32 " \
        "{%0,%1,%2,%3},{%4,%5,%6,%7},{%8,%9},{%0,%1,%2,%3};" \
        : "+f"((c)[0]),"+f"((c)[1]),"+f"((c)[2]),"+f"((c)[3]) \
        : "r"((a)[0]),"r"((a)[1]),"r"((a)[2]),"r"((a)[3]),"r"(b0),"r"(b1))

// Scratch
__device__ float g_qkv[(size_t)B_ * T_ * W3_];
__device__ float g_ff [(size_t)B_ * T_ * T_];
__device__ float g_ffsum[B_ * T_];
__device__ float g_att[(size_t)B_ * T_ * HD_];
__device__ float g_csum[B_ * CH_ * T_];

// ---------------------------------------------------------------------------
// fp32 GEMM with bias using packed f32x2 FMA.
// ---------------------------------------------------------------------------
__global__ __launch_bounds__(256) void sgemm_f2(
    const float* __restrict__ A, const float* __restrict__ Bm,
    const float* __restrict__ bias, float* __restrict__ Cm,
    int M, int N, int K)
{
    __shared__ float As[16][132];
    __shared__ float Bs[16][132];
    int tid = threadIdx.x;
    int tx = tid & 15, ty = tid >> 4;
    int row0 = blockIdx.y * 128, col0 = blockIdx.x * 128;
    int arow  = tid >> 1;
    int akoff = (tid & 1) * 8;
    int bkb   = tid >> 4;
    int bcol  = (tid & 15) * 8;
    const float* Ap = A + (size_t)(row0 + arow) * K + akoff;
    const float* Bp = Bm + (size_t)bkb * N + col0 + bcol;

    u64 acc[8][4];
#pragma unroll
    for (int i = 0; i < 8; i++)
#pragma unroll
        for (int j = 0; j < 4; j++) acc[i][j] = 0ull;

    for (int k0 = 0; k0 < K; k0 += 16) {
        float4 a0 = *(const float4*)(Ap + k0);
        float4 a1 = *(const float4*)(Ap + k0 + 4);
        float4 b0 = *(const float4*)(Bp + (size_t)k0 * N);
        float4 b1 = *(const float4*)(Bp + (size_t)k0 * N + 4);
        __syncthreads();
        As[akoff + 0][arow] = a0.x; As[akoff + 1][arow] = a0.y;
        As[akoff + 2][arow] = a0.z; As[akoff + 3][arow] = a0.w;
        As[akoff + 4][arow] = a1.x; As[akoff + 5][arow] = a1.y;
        As[akoff + 6][arow] = a1.z; As[akoff + 7][arow] = a1.w;
        *(float4*)&Bs[bkb][bcol]     = b0;
        *(float4*)&Bs[bkb][bcol + 4] = b1;
        __syncthreads();
#pragma unroll
        for (int kk = 0; kk < 16; kk++) {
            float4 av0 = *(const float4*)&As[kk][ty * 4];
            float4 av1 = *(const float4*)&As[kk][64 + ty * 4];
            u64 ad[8];
            ad[0] = dup2(av0.x); ad[1] = dup2(av0.y);
            ad[2] = dup2(av0.z); ad[3] = dup2(av0.w);
            ad[4] = dup2(av1.x); ad[5] = dup2(av1.y);
            ad[6] = dup2(av1.z); ad[7] = dup2(av1.w);
            u64 bx[4];
            bx[0] = *(const u64*)&Bs[kk][tx * 4];
            bx[1] = *(const u64*)&Bs[kk][tx * 4 + 2];
            bx[2] = *(const u64*)&Bs[kk][64 + tx * 4];
            bx[3] = *(const u64*)&Bs[kk][64 + tx * 4 + 2];
#pragma unroll
            for (int i = 0; i < 8; i++)
#pragma unroll
                for (int j = 0; j < 4; j++)
                    fma2(acc[i][j], ad[i], bx[j]);
        }
    }
#pragma unroll
    for (int i = 0; i < 8; i++) {
        int r = row0 + ((i < 4) ? (ty * 4 + i) : (64 + ty * 4 + (i - 4)));
#pragma unroll
        for (int g = 0; g < 2; g++) {
            int c = col0 + g * 64 + tx * 4;
            float2 p0 = up2(acc[i][g * 2 + 0]);
            float2 p1 = up2(acc[i][g * 2 + 1]);
            float4 o;
            o.x = p0.x + bias[c + 0];
            o.y = p0.y + bias[c + 1];
            o.z = p1.x + bias[c + 2];
            o.w = p1.y + bias[c + 3];
            *(float4*)&Cm[(size_t)r * N + c] = o;
        }
    }
}

// ---------------------------------------------------------------------------
// Head-0 selection scores (fp32 exact — feeds FF/M path).
// ---------------------------------------------------------------------------
__global__ __launch_bounds__(256) void scores_kernel(
    const float* __restrict__ qkv, float* __restrict__ S)
{
    int b = blockIdx.z, tb = blockIdx.y, sb = blockIdx.x;
    int t0 = tb * 64, s0 = sb * 64;
    int tid = threadIdx.x, tx = tid & 15, ty = tid >> 4;
    float* Sb = S + (size_t)b * T_ * T_;

    if (s0 >= t0 + 64) {
        float4 z = make_float4(0.f, 0.f, 0.f, 0.f);
#pragma unroll
        for (int i = 0; i < 4; i++)
            *(float4*)&Sb[(size_t)(t0 + ty * 4 + i) * T_ + s0 + tx * 4] = z;
        return;
    }

    __shared__ float Qs[64][68];
    __shared__ float Ks[64][68];
    const float* qb = qkv + ((size_t)b * T_ + t0) * W3_;
    const float* kb = qkv + ((size_t)b * T_ + s0) * W3_ + HD_;
    int lr = tid >> 4, lc = (tid & 15) * 4;
#pragma unroll
    for (int g = 0; g < 4; g++) {
        int r = lr + g * 16;
        *(float4*)&Qs[r][lc] = *(const float4*)&qb[(size_t)r * W3_ + lc];
        *(float4*)&Ks[r][lc] = *(const float4*)&kb[(size_t)r * W3_ + lc];
    }
    __syncthreads();

    float acc[4][4] = {};
#pragma unroll
    for (int dk = 0; dk < 16; dk++) {
        float4 qv[4], kv[4];
#pragma unroll
        for (int i = 0; i < 4; i++) qv[i] = *(const float4*)&Qs[ty * 4 + i][dk * 4];
#pragma unroll
        for (int j = 0; j < 4; j++) kv[j] = *(const float4*)&Ks[tx * 4 + j][dk * 4];
#pragma unroll
        for (int i = 0; i < 4; i++)
#pragma unroll
            for (int j = 0; j < 4; j++)
                acc[i][j] += qv[i].x * kv[j].x + qv[i].y * kv[j].y
                           + qv[i].z * kv[j].z + qv[i].w * kv[j].w;
    }
#pragma unroll
    for (int i = 0; i < 4; i++) {
        int t = t0 + ty * 4 + i;
        float out[4];
#pragma unroll
        for (int j = 0; j < 4; j++) {
            int s = s0 + tx * 4 + j;
            float v = acc[i][j] * 0.125f;
            out[j] = (s < t && s > 0) ? fmaxf(v, 0.f) : 0.f;
        }
        *(float4*)&Sb[(size_t)t * T_ + s0 + tx * 4] = *(float4*)out;
    }
}

// ---------------------------------------------------------------------------
// Two-pass exclusive column cumsum, 32 chunks of 64 rows.
// ---------------------------------------------------------------------------
__global__ __launch_bounds__(256) void cumsum_pass1(const float* __restrict__ S)
{
    int b = blockIdx.y, chunk = blockIdx.z;
    int s = blockIdx.x * 256 + threadIdx.x;
    const float* p = S + (size_t)b * T_ * T_ + (size_t)chunk * CL_ * T_ + s;
    float acc = 0.f;
#pragma unroll 8
    for (int t = 0; t < CL_; t++) acc += p[(size_t)t * T_];
    g_csum[(b * CH_ + chunk) * T_ + s] = acc;
}

__global__ __launch_bounds__(256) void cumsum_pass2(float* __restrict__ S)
{
    int b = blockIdx.y, chunk = blockIdx.z;
    int s = blockIdx.x * 256 + threadIdx.x;
    float base = 0.f;
    for (int c = 0; c < chunk; c++) base += g_csum[(b * CH_ + c) * T_ + s];
    float* p = S + (size_t)b * T_ * T_ + (size_t)chunk * CL_ * T_ + s;
    float acc = base;
#pragma unroll 8
    for (int t = 0; t < CL_; t++) {
        float v = p[(size_t)t * T_];
        p[(size_t)t * T_] = acc;
        acc += v;
    }
}

// ---------------------------------------------------------------------------
__global__ __launch_bounds__(256) void ffsum_kernel(const float* __restrict__ FF)
{
    int b = blockIdx.y, t = blockIdx.x;
    const float4* row = (const float4*)(FF + ((size_t)b * T_ + t) * T_);
    float s = 0.f;
    for (int j = threadIdx.x; j < T_ / 4; j += 256) {
        float4 v = row[j];
        s += fminf(v.x, 1.f) + fminf(v.y, 1.f) + fminf(v.z, 1.f) + fminf(v.w, 1.f);
    }
#pragma unroll
    for (int off = 16; off; off >>= 1) s += __shfl_xor_sync(0xffffffffu, s, off);
    __shared__ float red[8];
    int lane = threadIdx.x & 31, w = threadIdx.x >> 5;
    if (lane == 0) red[w] = s;
    __syncthreads();
    if (w == 0) {
        s = (lane < 8) ? red[lane] : 0.f;
#pragma unroll
        for (int off = 4; off; off >>= 1) s += __shfl_xor_sync(0xffffffffu, s, off);
        if (lane == 0) g_ffsum[b * T_ + t] = s;
    }
}

__global__ __launch_bounds__(256) void m_kernel(float* __restrict__ Mout)
{
    size_t idx4 = (size_t)blockIdx.x * 256 + threadIdx.x;
    size_t idx = idx4 * 4;
    int j = (int)(idx % T_);
    size_t r = idx / T_;
    int i = (int)(r % T_);
    int b = (int)(r / T_);
    float4 fs = *(const float4*)&g_ffsum[b * T_ + j];
    float fi = (float)i;
    float4 o = make_float4(fi - fs.x, fi - fs.y, fi - fs.z, fi - fs.w);
    *(float4*)&Mout[idx] = o;
}

// ---------------------------------------------------------------------------
// Flash attention with memory penalty — TF32 mma.sync, fp32 accumulate.
// Block: 128 q-rows × one (b,h); 8 warps (16 q-rows each); s-tiles of 128.
// Q/K/V/P stored in smem as tf32-rounded fp32. Fragments via scalar LDS
// (bank-conflict-free with strides 68 / 132).
// ---------------------------------------------------------------------------
#define FST 68
#define PST 132
#define QOF 0
#define KOF (128 * FST)
#define VOF (2 * 128 * FST)
#define POF (3 * 128 * FST)
#define FSMEM ((3 * 128 * FST + 128 * PST) * 4)   // 172032 B

__global__ __launch_bounds__(256) void flash_tf32(
    const float* __restrict__ qkv, const float* __restrict__ FF,
    float* __restrict__ Y)
{
    extern __shared__ __align__(16) float sm[];

    int tid = threadIdx.x;
    int lane = tid & 31, w = tid >> 5;
    int tb = gridDim.x - 1 - blockIdx.x;      // big tiles first
    int bh = blockIdx.y;
    int b = bh / H_, h = bh % H_;
    int t0 = tb * 128;

    const float* kvb = qkv + (size_t)b * T_ * W3_;

    // ---- load Q tile -> tf32-rounded smem ----
    {
        int r = tid >> 1, c0 = (tid & 1) * 32;
        const float* qp = kvb + (size_t)(t0 + r) * W3_ + h * D_ + c0;
        float* dst = sm + QOF + r * FST + c0;
#pragma unroll
        for (int u = 0; u < 8; u++) {
            float4 v = *(const float4*)(qp + u * 4);
            dst[u * 4 + 0] = __uint_as_float(tf32r(v.x));
            dst[u * 4 + 1] = __uint_as_float(tf32r(v.y));
            dst[u * 4 + 2] = __uint_as_float(tf32r(v.z));
            dst[u * 4 + 3] = __uint_as_float(tf32r(v.w));
        }
    }
    __syncthreads();

    // ---- Q A-fragments: 8 k-chunks × 4 regs ----
    int rq = 16 * w + (lane >> 2);
    int cq = lane & 3;
    uint32_t aq[8][4];
#pragma unroll
    for (int kc = 0; kc < 8; kc++) {
        const float* q0 = sm + QOF + rq * FST + kc * 8 + cq;
        aq[kc][0] = __float_as_uint(q0[0]);
        aq[kc][1] = __float_as_uint(q0[8 * FST]);
        aq[kc][2] = __float_as_uint(q0[4]);
        aq[kc][3] = __float_as_uint(q0[8 * FST + 4]);
    }

    float m0 = -1e30f, m1 = -1e30f, l0 = 0.f, l1 = 0.f;
    float o[8][4];
#pragma unroll
    for (int i = 0; i < 8; i++)
#pragma unroll
        for (int j = 0; j < 4; j++) o[i][j] = 0.f;

    int qr0 = t0 + 16 * w + (lane >> 2);
    const float* ff0 = FF + (size_t)b * T_ * T_ + (size_t)qr0 * T_;
    const float* ff1 = ff0 + 8 * T_;
    int cl = (lane & 3) << 1;

    for (int kb = 0; kb <= tb; kb++) {
        int s0 = kb * 128;
        __syncthreads();
        // ---- load K,V tiles ----
        {
            int r = tid >> 1, c0 = (tid & 1) * 32;
            const float* kp = kvb + (size_t)(s0 + r) * W3_ + HD_     + h * D_ + c0;
            const float* vp = kvb + (size_t)(s0 + r) * W3_ + 2 * HD_ + h * D_ + c0;
            float* dk = sm + KOF + r * FST + c0;
            float* dv = sm + VOF + r * FST + c0;
#pragma unroll
            for (int u = 0; u < 8; u++) {
                float4 kv = *(const float4*)(kp + u * 4);
                float4 vv = *(const float4*)(vp + u * 4);
                dk[u * 4 + 0] = __uint_as_float(tf32r(kv.x));
                dk[u * 4 + 1] = __uint_as_float(tf32r(kv.y));
                dk[u * 4 + 2] = __uint_as_float(tf32r(kv.z));
                dk[u * 4 + 3] = __uint_as_float(tf32r(kv.w));
                dv[u * 4 + 0] = __uint_as_float(tf32r(vv.x));
                dv[u * 4 + 1] = __uint_as_float(tf32r(vv.y));
                dv[u * 4 + 2] = __uint_as_float(tf32r(vv.z));
                dv[u * 4 + 3] = __uint_as_float(tf32r(vv.w));
            }
        }
        __syncthreads();

        // ---- QK^T over 16 n8-tiles ----
        float acc[16][4];
#pragma unroll
        for (int i = 0; i < 16; i++)
#pragma unroll
            for (int j = 0; j < 4; j++) acc[i][j] = 0.f;

#pragma unroll
        for (int kc = 0; kc < 8; kc++) {
#pragma unroll
            for (int g = 0; g < 16; g++) {
                const float* kpK = sm + KOF + (g * 8 + (lane >> 2)) * FST
                                 + kc * 8 + (lane & 3);
                uint32_t b0 = __float_as_uint(kpK[0]);
                uint32_t b1 = __float_as_uint(kpK[4]);
                MMA_TF32(acc[g], aq[kc], b0, b1);
            }
        }

        // ---- logits: scale, subtract FF, causal mask ----
        bool diag = (kb == tb);
#pragma unroll
        for (int t = 0; t < 16; t++) {
            int sc = s0 + 8 * t + cl;
            float2 fa = *(const float2*)(ff0 + sc);
            float2 fb = *(const float2*)(ff1 + sc);
            acc[t][0] = acc[t][0] * 0.125f - fa.x;
            acc[t][1] = acc[t][1] * 0.125f - fa.y;
            acc[t][2] = acc[t][2] * 0.125f - fb.x;
            acc[t][3] = acc[t][3] * 0.125f - fb.y;
            if (diag) {
                if (sc     > qr0)     acc[t][0] = -1e30f;
                if (sc + 1 > qr0)     acc[t][1] = -1e30f;
                if (sc     > qr0 + 8) acc[t][2] = -1e30f;
                if (sc + 1 > qr0 + 8) acc[t][3] = -1e30f;
            }
        }

        // ---- online softmax ----
        float mx0 = -1e30f, mx1 = -1e30f;
#pragma unroll
        for (int t = 0; t < 16; t++) {
            mx0 = fmaxf(mx0, fmaxf(acc[t][0], acc[t][1]));
            mx1 = fmaxf(mx1, fmaxf(acc[t][2], acc[t][3]));
        }
        mx0 = fmaxf(mx0, __shfl_xor_sync(0xffffffffu, mx0, 1));
        mx0 = fmaxf(mx0, __shfl_xor_sync(0xffffffffu, mx0, 2));
        mx1 = fmaxf(mx1, __shfl_xor_sync(0xffffffffu, mx1, 1));
        mx1 = fmaxf(mx1, __shfl_xor_sync(0xffffffffu, mx1, 2));
        float mn0 = fmaxf(m0, mx0), mn1 = fmaxf(m1, mx1);
        float c0 = __expf(m0 - mn0), c1 = __expf(m1 - mn1);
        m0 = mn0; m1 = mn1;

        float s0r = 0.f, s1r = 0.f;
#pragma unroll
        for (int t = 0; t < 16; t++) {
            acc[t][0] = __expf(acc[t][0] - mn0);
            acc[t][1] = __expf(acc[t][1] - mn0);
            acc[t][2] = __expf(acc[t][2] - mn1);
            acc[t][3] = __expf(acc[t][3] - mn1);
            s0r += acc[t][0] + acc[t][1];
            s1r += acc[t][2] + acc[t][3];
        }
        s0r += __shfl_xor_sync(0xffffffffu, s0r, 1);
        s0r += __shfl_xor_sync(0xffffffffu, s0r, 2);
        s1r += __shfl_xor_sync(0xffffffffu, s1r, 1);
        s1r += __shfl_xor_sync(0xffffffffu, s1r, 2);
        l0 = l0 * c0 + s0r;
        l1 = l1 * c1 + s1r;

#pragma unroll
        for (int i = 0; i < 8; i++) {
            o[i][0] *= c0; o[i][1] *= c0;
            o[i][2] *= c1; o[i][3] *= c1;
        }

        // ---- store P (tf32-rounded) to per-warp smem rows ----
        {
            float* pr0 = sm + POF + (16 * w + (lane >> 2)) * PST + cl;
            float* pr1 = pr0 + 8 * PST;
#pragma unroll
            for (int t = 0; t < 16; t++) {
                pr0[8 * t + 0] = __uint_as_float(tf32r(acc[t][0]));
                pr0[8 * t + 1] = __uint_as_float(tf32r(acc[t][1]));
                pr1[8 * t + 0] = __uint_as_float(tf32r(acc[t][2]));
                pr1[8 * t + 1] = __uint_as_float(tf32r(acc[t][3]));
            }
        }
        __syncwarp();

        // ---- PV: o += P @ V ----
#pragma unroll
        for (int kc = 0; kc < 16; kc++) {
            const float* pp = sm + POF + rq * PST + kc * 8 + cq;
            uint32_t ap[4];
            ap[0] = __float_as_uint(pp[0]);
            ap[1] = __float_as_uint(pp[8 * PST]);
            ap[2] = __float_as_uint(pp[4]);
            ap[3] = __float_as_uint(pp[8 * PST + 4]);
            const float* vrow0 = sm + VOF + (kc * 8 + (lane & 3)) * FST + (lane >> 2);
#pragma unroll
            for (int dg = 0; dg < 8; dg++) {
                uint32_t b0 = __float_as_uint(vrow0[dg * 8]);
                uint32_t b1 = __float_as_uint(vrow0[4 * FST + dg * 8]);
                MMA_TF32(o[dg], ap, b0, b1);
            }
        }
        __syncwarp();
    }

    // ---- write y ----
    float i0 = 1.f / l0, i1 = 1.f / l1;
    float* yb = Y + (size_t)(b * T_ + qr0) * HD_ + h * D_;
#pragma unroll
    for (int dg = 0; dg < 8; dg++) {
        int dc = 8 * dg + cl;
        float2 w0 = make_float2(o[dg][0] * i0, o[dg][1] * i0);
        float2 w1 = make_float2(o[dg][2] * i1, o[dg][3] * i1);
        *(float2*)(yb + dc) = w0;
        *(float2*)(yb + 8 * (size_t)HD_ + dc) = w1;
    }
}

// ---------------------------------------------------------------------------
extern "C" void kernel_launch(void* const* d_in, const int* in_sizes, int n_in,
                              void* d_out, int out_size)
{
    const float* x      = (const float*)d_in[0];
    const float* W_attn = (const float*)d_in[1];
    const float* b_attn = (const float*)d_in[2];
    const float* W_proj = (const float*)d_in[3];
    const float* b_proj = (const float*)d_in[4];

    float* out   = (float*)d_out;
    float* y_out = out;
    float* m_out = out + (size_t)B_ * T_ * C_;

    float *qkv, *ff, *att;
    cudaGetSymbolAddress((void**)&qkv, g_qkv);
    cudaGetSymbolAddress((void**)&ff,  g_ff);
    cudaGetSymbolAddress((void**)&att, g_att);

    dim3 blk(256);

    sgemm_f2<<<dim3(W3_ / 128, (B_ * T_) / 128), blk>>>(
        x, W_attn, b_attn, qkv, B_ * T_, W3_, C_);

    scores_kernel<<<dim3(T_ / 64, T_ / 64, B_), blk>>>(qkv, ff);

    cumsum_pass1<<<dim3(T_ / 256, B_, CH_), blk>>>(ff);
    cumsum_pass2<<<dim3(T_ / 256, B_, CH_), blk>>>(ff);

    ffsum_kernel<<<dim3(T_, B_), blk>>>(ff);

    m_kernel<<<dim3((unsigned)(((size_t)B_ * T_ * T_) / 1024)), blk>>>(m_out);

    cudaFuncSetAttribute(flash_tf32,
                         cudaFuncAttributeMaxDynamicSharedMemorySize, FSMEM);
    flash_tf32<<<dim3(T_ / 128, B_ * H_), blk, FSMEM>>>(qkv, ff, att);

    sgemm_f2<<<dim3(C_ / 128, (B_ * T_) / 128), blk>>>(
        att, W_proj, b_proj, y_out, B_ * T_, C_, HD_);
}

// round 5
// speedup vs baseline: 2.3954x; 1.2201x over previous
#include <cuda_runtime.h>
#include <cuda_bf16.h>
#include <cstdint>

#define B_  2
#define T_  2048
#define C_  768
#define H_  12
#define D_  64
#define HD_ 768
#define W3_ 2304   // 3*HD
#define CH_ 64
#define CL_ (T_/CH_)   // 32

typedef unsigned long long u64;

// ---- packed f32x2 helpers -------------------------------------------------
__device__ __forceinline__ u64 pk2(float lo, float hi) {
    u64 r; asm("mov.b64 %0,{%1,%2};" : "=l"(r) : "f"(lo), "f"(hi)); return r;
}
__device__ __forceinline__ u64 dup2(float v) { return pk2(v, v); }
__device__ __forceinline__ float2 up2(u64 v) {
    float2 r; asm("mov.b64 {%0,%1},%2;" : "=f"(r.x), "=f"(r.y) : "l"(v)); return r;
}
__device__ __forceinline__ void fma2(u64& d, u64 a, u64 b) {
    asm("fma.rn.f32x2 %0,%1,%2,%3;" : "=l"(d) : "l"(a), "l"(b), "l"(d));
}

// ---- tf32 helpers -----------------------------------------------------------
__device__ __forceinline__ uint32_t tf32r(float x) {
    uint32_t r; asm("cvt.rna.tf32.f32 %0,%1;" : "=r"(r) : "f"(x)); return r;
}
#define MMA_TF32(c,a,b0,b1) \
    asm volatile("mma.sync.aligned.m16n8k8.row.col.f32.tf32.tf32.f32 " \
        "{%0,%1,%2,%3},{%4,%5,%6,%7},{%8,%9},{%0,%1,%2,%3};" \
        : "+f"((c)[0]),"+f"((c)[1]),"+f"((c)[2]),"+f"((c)[3]) \
        : "r"((a)[0]),"r"((a)[1]),"r"((a)[2]),"r"((a)[3]),"r"(b0),"r"(b1))

// Scratch
__device__ float g_qkv[(size_t)B_ * T_ * W3_];
__device__ float g_ff [(size_t)B_ * T_ * T_];
__device__ float g_ffsum[B_ * T_];
__device__ float g_att[(size_t)B_ * T_ * HD_];
__device__ float g_csum[B_ * CH_ * T_];

// ---------------------------------------------------------------------------
// TF32 tensor-core GEMM with bias: C[M,N] = A[M,K] @ B[K,N] + bias[N]
// Tile 128x128, BK=16, 256 threads (8 warps), warp = 16 rows x 128 cols.
// ---------------------------------------------------------------------------
#define AST 20
#define BST 136
__global__ __launch_bounds__(256) void sgemm_tf32(
    const float* __restrict__ A, const float* __restrict__ Bm,
    const float* __restrict__ bias, float* __restrict__ Cm,
    int M, int N, int K)
{
    __shared__ float As[128 * AST];
    __shared__ float Bs[16 * BST];
    int tid = threadIdx.x, lane = tid & 31, w = tid >> 5;
    int gid = lane >> 2, tig = lane & 3;
    int row0 = blockIdx.y * 128, col0 = blockIdx.x * 128;

    int arow = tid >> 1, acol = (tid & 1) * 8;
    int brow = tid >> 4, bcol = (tid & 15) * 8;
    const float* Ap = A + (size_t)(row0 + arow) * K + acol;
    const float* Bp = Bm + (size_t)brow * N + col0 + bcol;

    float c[16][4];
#pragma unroll
    for (int g = 0; g < 16; g++)
#pragma unroll
        for (int j = 0; j < 4; j++) c[g][j] = 0.f;

    float4 a0 = *(const float4*)(Ap);
    float4 a1 = *(const float4*)(Ap + 4);
    float4 b0 = *(const float4*)(Bp);
    float4 b1 = *(const float4*)(Bp + 4);

    for (int k0 = 0; k0 < K; k0 += 16) {
        __syncthreads();
        {
            float* ad = As + arow * AST + acol;
            ad[0] = __uint_as_float(tf32r(a0.x));
            ad[1] = __uint_as_float(tf32r(a0.y));
            ad[2] = __uint_as_float(tf32r(a0.z));
            ad[3] = __uint_as_float(tf32r(a0.w));
            ad[4] = __uint_as_float(tf32r(a1.x));
            ad[5] = __uint_as_float(tf32r(a1.y));
            ad[6] = __uint_as_float(tf32r(a1.z));
            ad[7] = __uint_as_float(tf32r(a1.w));
            float* bd = Bs + brow * BST + bcol;
            bd[0] = __uint_as_float(tf32r(b0.x));
            bd[1] = __uint_as_float(tf32r(b0.y));
            bd[2] = __uint_as_float(tf32r(b0.z));
            bd[3] = __uint_as_float(tf32r(b0.w));
            bd[4] = __uint_as_float(tf32r(b1.x));
            bd[5] = __uint_as_float(tf32r(b1.y));
            bd[6] = __uint_as_float(tf32r(b1.z));
            bd[7] = __uint_as_float(tf32r(b1.w));
        }
        __syncthreads();
        if (k0 + 16 < K) {
            a0 = *(const float4*)(Ap + k0 + 16);
            a1 = *(const float4*)(Ap + k0 + 20);
            b0 = *(const float4*)(Bp + (size_t)(k0 + 16) * N);
            b1 = *(const float4*)(Bp + (size_t)(k0 + 16) * N + 4);
        }
#pragma unroll
        for (int kc = 0; kc < 2; kc++) {
            uint32_t af[4];
            const float* ab = As + (16 * w + gid) * AST + kc * 8 + tig;
            af[0] = __float_as_uint(ab[0]);
            af[1] = __float_as_uint(ab[8 * AST]);
            af[2] = __float_as_uint(ab[4]);
            af[3] = __float_as_uint(ab[8 * AST + 4]);
            const float* bb = Bs + (kc * 8 + tig) * BST + gid;
#pragma unroll
            for (int g = 0; g < 16; g++) {
                uint32_t bf0 = __float_as_uint(bb[g * 8]);
                uint32_t bf1 = __float_as_uint(bb[4 * BST + g * 8]);
                MMA_TF32(c[g], af, bf0, bf1);
            }
        }
    }

    int crow = row0 + 16 * w + gid;
#pragma unroll
    for (int g = 0; g < 16; g++) {
        int cc = col0 + g * 8 + 2 * tig;
        float bx0 = bias[cc], bx1 = bias[cc + 1];
        float2 w0 = make_float2(c[g][0] + bx0, c[g][1] + bx1);
        float2 w1 = make_float2(c[g][2] + bx0, c[g][3] + bx1);
        *(float2*)&Cm[(size_t)crow * N + cc] = w0;
        *(float2*)&Cm[(size_t)(crow + 8) * N + cc] = w1;
    }
}

// ---------------------------------------------------------------------------
// Exact fp32 patch GEMM for head-0 q,k columns: cols [0,64) and [768,832).
// Tile 64x64, BK=16, 256 threads, f32x2.
// ---------------------------------------------------------------------------
__global__ __launch_bounds__(256) void qk0_patch(
    const float* __restrict__ x, const float* __restrict__ W,
    const float* __restrict__ bias, float* __restrict__ qkv)
{
    __shared__ float As[16][68];
    __shared__ float Bs[16][68];
    int tid = threadIdx.x;
    int tx = tid & 15, ty = tid >> 4;
    int row0 = blockIdx.y * 64;
    int colbase = blockIdx.x * 768;            // 0 (q0) or 768 (k0)
    int arow = tid >> 2, acol = (tid & 3) * 4;
    int brow = tid >> 4, bcol = (tid & 15) * 4;
    const float* Ap = x + (size_t)(row0 + arow) * C_ + acol;
    const float* Bp = W + (size_t)brow * W3_ + colbase + bcol;

    u64 acc[4][2];
#pragma unroll
    for (int i = 0; i < 4; i++) { acc[i][0] = 0ull; acc[i][1] = 0ull; }

    for (int k0 = 0; k0 < C_; k0 += 16) {
        float4 a = *(const float4*)(Ap + k0);
        float4 b = *(const float4*)(Bp + (size_t)k0 * W3_);
        __syncthreads();
        As[acol + 0][arow] = a.x; As[acol + 1][arow] = a.y;
        As[acol + 2][arow] = a.z; As[acol + 3][arow] = a.w;
        *(float4*)&Bs[brow][bcol] = b;
        __syncthreads();
#pragma unroll
        for (int kk = 0; kk < 16; kk++) {
            float4 av = *(const float4*)&As[kk][ty * 4];
            u64 ad[4];
            ad[0] = dup2(av.x); ad[1] = dup2(av.y);
            ad[2] = dup2(av.z); ad[3] = dup2(av.w);
            u64 bx0 = *(const u64*)&Bs[kk][tx * 4];
            u64 bx1 = *(const u64*)&Bs[kk][tx * 4 + 2];
#pragma unroll
            for (int i = 0; i < 4; i++) {
                fma2(acc[i][0], ad[i], bx0);
                fma2(acc[i][1], ad[i], bx1);
            }
        }
    }
#pragma unroll
    for (int i = 0; i < 4; i++) {
        int r = row0 + ty * 4 + i;
        int cc = colbase + tx * 4;
        float2 p0 = up2(acc[i][0]);
        float2 p1 = up2(acc[i][1]);
        float4 o;
        o.x = p0.x + bias[cc + 0];
        o.y = p0.y + bias[cc + 1];
        o.z = p1.x + bias[cc + 2];
        o.w = p1.y + bias[cc + 3];
        *(float4*)&qkv[(size_t)r * W3_ + cc] = o;
    }
}

// ---------------------------------------------------------------------------
// Head-0 selection scores (fp32 exact). Only lower-triangular tiles computed;
// upper region of S is never written (cumsum predicates by t>s).
// ---------------------------------------------------------------------------
__global__ __launch_bounds__(256) void scores_kernel(
    const float* __restrict__ qkv, float* __restrict__ S)
{
    int b = blockIdx.z, tb = blockIdx.y, sb = blockIdx.x;
    int t0 = tb * 64, s0 = sb * 64;
    if (s0 > t0) return;                     // strictly upper tile: skip
    int tid = threadIdx.x, tx = tid & 15, ty = tid >> 4;
    float* Sb = S + (size_t)b * T_ * T_;

    __shared__ float Qs[64][68];
    __shared__ float Ks[64][68];
    const float* qb = qkv + ((size_t)b * T_ + t0) * W3_;
    const float* kb = qkv + ((size_t)b * T_ + s0) * W3_ + HD_;
    int lr = tid >> 4, lc = (tid & 15) * 4;
#pragma unroll
    for (int g = 0; g < 4; g++) {
        int r = lr + g * 16;
        *(float4*)&Qs[r][lc] = *(const float4*)&qb[(size_t)r * W3_ + lc];
        *(float4*)&Ks[r][lc] = *(const float4*)&kb[(size_t)r * W3_ + lc];
    }
    __syncthreads();

    float acc[4][4] = {};
#pragma unroll
    for (int dk = 0; dk < 16; dk++) {
        float4 qv[4], kv[4];
#pragma unroll
        for (int i = 0; i < 4; i++) qv[i] = *(const float4*)&Qs[ty * 4 + i][dk * 4];
#pragma unroll
        for (int j = 0; j < 4; j++) kv[j] = *(const float4*)&Ks[tx * 4 + j][dk * 4];
#pragma unroll
        for (int i = 0; i < 4; i++)
#pragma unroll
            for (int j = 0; j < 4; j++)
                acc[i][j] += qv[i].x * kv[j].x + qv[i].y * kv[j].y
                           + qv[i].z * kv[j].z + qv[i].w * kv[j].w;
    }
#pragma unroll
    for (int i = 0; i < 4; i++) {
        int t = t0 + ty * 4 + i;
        float out[4];
#pragma unroll
        for (int j = 0; j < 4; j++) {
            int s = s0 + tx * 4 + j;
            float v = acc[i][j] * 0.125f;
            out[j] = (s < t && s > 0) ? fmaxf(v, 0.f) : 0.f;
        }
        *(float4*)&Sb[(size_t)t * T_ + s0 + tx * 4] = *(float4*)out;
    }
}

// ---------------------------------------------------------------------------
// Two-pass exclusive column cumsum with triangular predication.
// S[t,s] is only valid where t > s; treat everything else as 0.
// ---------------------------------------------------------------------------
__global__ __launch_bounds__(256) void cumsum_pass1(const float* __restrict__ S)
{
    int b = blockIdx.y, chunk = blockIdx.z;
    int c0 = chunk * CL_;
    int s0 = blockIdx.x * 256;
    int s = s0 + threadIdx.x;
    float* dst = &g_csum[(b * CH_ + chunk) * T_ + s];
    if (s0 >= c0 + CL_ - 1) { *dst = 0.f; return; }   // all rows t <= s
    const float* p = S + (size_t)b * T_ * T_ + (size_t)c0 * T_ + s;
    float acc = 0.f;
#pragma unroll 8
    for (int t = 0; t < CL_; t++) {
        float v = p[(size_t)t * T_];
        acc += (c0 + t > s) ? v : 0.f;
    }
    *dst = acc;
}

__global__ __launch_bounds__(256) void cumsum_pass2(float* __restrict__ S)
{
    int b = blockIdx.y, chunk = blockIdx.z;
    int c0 = chunk * CL_;
    int s0 = blockIdx.x * 256;
    if (s0 >= c0 + CL_) return;              // no entries with s <= t
    int s = s0 + threadIdx.x;
    float base = 0.f;
    for (int c = 0; c < chunk; c++) base += g_csum[(b * CH_ + c) * T_ + s];
    float* p = S + (size_t)b * T_ * T_ + (size_t)c0 * T_ + s;
    float acc = base;
#pragma unroll 8
    for (int t = 0; t < CL_; t++) {
        float v = p[(size_t)t * T_];
        p[(size_t)t * T_] = acc;
        acc += (c0 + t > s) ? v : 0.f;
    }
}

// ---------------------------------------------------------------------------
// FF_sum[b,t] = sum_{s<=t} min(FF[b,t,s], 1)   (FF == 0 for s >= t-1)
// ---------------------------------------------------------------------------
__global__ __launch_bounds__(256) void ffsum_kernel(const float* __restrict__ FF)
{
    int b = blockIdx.y, t = blockIdx.x;
    const float4* row = (const float4*)(FF + ((size_t)b * T_ + t) * T_);
    int n4 = (t >> 2) + 1;
    float s = 0.f;
    for (int j = threadIdx.x; j < n4; j += 256) {
        float4 v = row[j];
        int sb = j * 4;
        s += (sb     <= t ? fminf(v.x, 1.f) : 0.f)
           + (sb + 1 <= t ? fminf(v.y, 1.f) : 0.f)
           + (sb + 2 <= t ? fminf(v.z, 1.f) : 0.f)
           + (sb + 3 <= t ? fminf(v.w, 1.f) : 0.f);
    }
#pragma unroll
    for (int off = 16; off; off >>= 1) s += __shfl_xor_sync(0xffffffffu, s, off);
    __shared__ float red[8];
    int lane = threadIdx.x & 31, w = threadIdx.x >> 5;
    if (lane == 0) red[w] = s;
    __syncthreads();
    if (w == 0) {
        s = (lane < 8) ? red[lane] : 0.f;
#pragma unroll
        for (int off = 4; off; off >>= 1) s += __shfl_xor_sync(0xffffffffu, s, off);
        if (lane == 0) g_ffsum[b * T_ + t] = s;
    }
}

__global__ __launch_bounds__(256) void m_kernel(float* __restrict__ Mout)
{
    size_t idx4 = (size_t)blockIdx.x * 256 + threadIdx.x;
    size_t idx = idx4 * 4;
    int j = (int)(idx % T_);
    size_t r = idx / T_;
    int i = (int)(r % T_);
    int b = (int)(r / T_);
    float4 fs = *(const float4*)&g_ffsum[b * T_ + j];
    float fi = (float)i;
    float4 o = make_float4(fi - fs.x, fi - fs.y, fi - fs.z, fi - fs.w);
    *(float4*)&Mout[idx] = o;
}

// ---------------------------------------------------------------------------
// Flash attention with memory penalty — TF32 mma.sync (unchanged from R4).
// ---------------------------------------------------------------------------
#define FST 68
#define PST 132
#define QOF 0
#define KOF (128 * FST)
#define VOF (2 * 128 * FST)
#define POF (3 * 128 * FST)
#define FSMEM ((3 * 128 * FST + 128 * PST) * 4)

__global__ __launch_bounds__(256) void flash_tf32(
    const float* __restrict__ qkv, const float* __restrict__ FF,
    float* __restrict__ Y)
{
    extern __shared__ __align__(16) float sm[];

    int tid = threadIdx.x;
    int lane = tid & 31, w = tid >> 5;
    int tb = gridDim.x - 1 - blockIdx.x;
    int bh = blockIdx.y;
    int b = bh / H_, h = bh % H_;
    int t0 = tb * 128;

    const float* kvb = qkv + (size_t)b * T_ * W3_;

    {
        int r = tid >> 1, c0 = (tid & 1) * 32;
        const float* qp = kvb + (size_t)(t0 + r) * W3_ + h * D_ + c0;
        float* dst = sm + QOF + r * FST + c0;
#pragma unroll
        for (int u = 0; u < 8; u++) {
            float4 v = *(const float4*)(qp + u * 4);
            dst[u * 4 + 0] = __uint_as_float(tf32r(v.x));
            dst[u * 4 + 1] = __uint_as_float(tf32r(v.y));
            dst[u * 4 + 2] = __uint_as_float(tf32r(v.z));
            dst[u * 4 + 3] = __uint_as_float(tf32r(v.w));
        }
    }
    __syncthreads();

    int rq = 16 * w + (lane >> 2);
    int cq = lane & 3;
    uint32_t aq[8][4];
#pragma unroll
    for (int kc = 0; kc < 8; kc++) {
        const float* q0 = sm + QOF + rq * FST + kc * 8 + cq;
        aq[kc][0] = __float_as_uint(q0[0]);
        aq[kc][1] = __float_as_uint(q0[8 * FST]);
        aq[kc][2] = __float_as_uint(q0[4]);
        aq[kc][3] = __float_as_uint(q0[8 * FST + 4]);
    }

    float m0 = -1e30f, m1 = -1e30f, l0 = 0.f, l1 = 0.f;
    float o[8][4];
#pragma unroll
    for (int i = 0; i < 8; i++)
#pragma unroll
        for (int j = 0; j < 4; j++) o[i][j] = 0.f;

    int qr0 = t0 + 16 * w + (lane >> 2);
    const float* ff0 = FF + (size_t)b * T_ * T_ + (size_t)qr0 * T_;
    const float* ff1 = ff0 + 8 * T_;
    int cl = (lane & 3) << 1;

    for (int kb = 0; kb <= tb; kb++) {
        int s0 = kb * 128;
        __syncthreads();
        {
            int r = tid >> 1, c0 = (tid & 1) * 32;
            const float* kp = kvb + (size_t)(s0 + r) * W3_ + HD_     + h * D_ + c0;
            const float* vp = kvb + (size_t)(s0 + r) * W3_ + 2 * HD_ + h * D_ + c0;
            float* dk = sm + KOF + r * FST + c0;
            float* dv = sm + VOF + r * FST + c0;
#pragma unroll
            for (int u = 0; u < 8; u++) {
                float4 kv = *(const float4*)(kp + u * 4);
                float4 vv = *(const float4*)(vp + u * 4);
                dk[u * 4 + 0] = __uint_as_float(tf32r(kv.x));
                dk[u * 4 + 1] = __uint_as_float(tf32r(kv.y));
                dk[u * 4 + 2] = __uint_as_float(tf32r(kv.z));
                dk[u * 4 + 3] = __uint_as_float(tf32r(kv.w));
                dv[u * 4 + 0] = __uint_as_float(tf32r(vv.x));
                dv[u * 4 + 1] = __uint_as_float(tf32r(vv.y));
                dv[u * 4 + 2] = __uint_as_float(tf32r(vv.z));
                dv[u * 4 + 3] = __uint_as_float(tf32r(vv.w));
            }
        }
        __syncthreads();

        float acc[16][4];
#pragma unroll
        for (int i = 0; i < 16; i++)
#pragma unroll
            for (int j = 0; j < 4; j++) acc[i][j] = 0.f;

#pragma unroll
        for (int kc = 0; kc < 8; kc++) {
#pragma unroll
            for (int g = 0; g < 16; g++) {
                const float* kpK = sm + KOF + (g * 8 + (lane >> 2)) * FST
                                 + kc * 8 + (lane & 3);
                uint32_t b0 = __float_as_uint(kpK[0]);
                uint32_t b1 = __float_as_uint(kpK[4]);
                MMA_TF32(acc[g], aq[kc], b0, b1);
            }
        }

        bool diag = (kb == tb);
#pragma unroll
        for (int t = 0; t < 16; t++) {
            int sc = s0 + 8 * t + cl;
            float2 fa = *(const float2*)(ff0 + sc);
            float2 fb = *(const float2*)(ff1 + sc);
            acc[t][0] = acc[t][0] * 0.125f - fa.x;
            acc[t][1] = acc[t][1] * 0.125f - fa.y;
            acc[t][2] = acc[t][2] * 0.125f - fb.x;
            acc[t][3] = acc[t][3] * 0.125f - fb.y;
            if (diag) {
                if (sc     > qr0)     acc[t][0] = -1e30f;
                if (sc + 1 > qr0)     acc[t][1] = -1e30f;
                if (sc     > qr0 + 8) acc[t][2] = -1e30f;
                if (sc + 1 > qr0 + 8) acc[t][3] = -1e30f;
            }
        }

        float mx0 = -1e30f, mx1 = -1e30f;
#pragma unroll
        for (int t = 0; t < 16; t++) {
            mx0 = fmaxf(mx0, fmaxf(acc[t][0], acc[t][1]));
            mx1 = fmaxf(mx1, fmaxf(acc[t][2], acc[t][3]));
        }
        mx0 = fmaxf(mx0, __shfl_xor_sync(0xffffffffu, mx0, 1));
        mx0 = fmaxf(mx0, __shfl_xor_sync(0xffffffffu, mx0, 2));
        mx1 = fmaxf(mx1, __shfl_xor_sync(0xffffffffu, mx1, 1));
        mx1 = fmaxf(mx1, __shfl_xor_sync(0xffffffffu, mx1, 2));
        float mn0 = fmaxf(m0, mx0), mn1 = fmaxf(m1, mx1);
        float c0 = __expf(m0 - mn0), c1 = __expf(m1 - mn1);
        m0 = mn0; m1 = mn1;

        float s0r = 0.f, s1r = 0.f;
#pragma unroll
        for (int t = 0; t < 16; t++) {
            acc[t][0] = __expf(acc[t][0] - mn0);
            acc[t][1] = __expf(acc[t][1] - mn0);
            acc[t][2] = __expf(acc[t][2] - mn1);
            acc[t][3] = __expf(acc[t][3] - mn1);
            s0r += acc[t][0] + acc[t][1];
            s1r += acc[t][2] + acc[t][3];
        }
        s0r += __shfl_xor_sync(0xffffffffu, s0r, 1);
        s0r += __shfl_xor_sync(0xffffffffu, s0r, 2);
        s1r += __shfl_xor_sync(0xffffffffu, s1r, 1);
        s1r += __shfl_xor_sync(0xffffffffu, s1r, 2);
        l0 = l0 * c0 + s0r;
        l1 = l1 * c1 + s1r;

#pragma unroll
        for (int i = 0; i < 8; i++) {
            o[i][0] *= c0; o[i][1] *= c0;
            o[i][2] *= c1; o[i][3] *= c1;
        }

        {
            float* pr0 = sm + POF + (16 * w + (lane >> 2)) * PST + cl;
            float* pr1 = pr0 + 8 * PST;
#pragma unroll
            for (int t = 0; t < 16; t++) {
                pr0[8 * t + 0] = __uint_as_float(tf32r(acc[t][0]));
                pr0[8 * t + 1] = __uint_as_float(tf32r(acc[t][1]));
                pr1[8 * t + 0] = __uint_as_float(tf32r(acc[t][2]));
                pr1[8 * t + 1] = __uint_as_float(tf32r(acc[t][3]));
            }
        }
        __syncwarp();

#pragma unroll
        for (int kc = 0; kc < 16; kc++) {
            const float* pp = sm + POF + rq * PST + kc * 8 + cq;
            uint32_t ap[4];
            ap[0] = __float_as_uint(pp[0]);
            ap[1] = __float_as_uint(pp[8 * PST]);
            ap[2] = __float_as_uint(pp[4]);
            ap[3] = __float_as_uint(pp[8 * PST + 4]);
            const float* vrow0 = sm + VOF + (kc * 8 + (lane & 3)) * FST + (lane >> 2);
#pragma unroll
            for (int dg = 0; dg < 8; dg++) {
                uint32_t b0 = __float_as_uint(vrow0[dg * 8]);
                uint32_t b1 = __float_as_uint(vrow0[4 * FST + dg * 8]);
                MMA_TF32(o[dg], ap, b0, b1);
            }
        }
        __syncwarp();
    }

    float i0 = 1.f / l0, i1 = 1.f / l1;
    float* yb = Y + (size_t)(b * T_ + qr0) * HD_ + h * D_;
#pragma unroll
    for (int dg = 0; dg < 8; dg++) {
        int dc = 8 * dg + cl;
        float2 w0 = make_float2(o[dg][0] * i0, o[dg][1] * i0);
        float2 w1 = make_float2(o[dg][2] * i1, o[dg][3] * i1);
        *(float2*)(yb + dc) = w0;
        *(float2*)(yb + 8 * (size_t)HD_ + dc) = w1;
    }
}

// ---------------------------------------------------------------------------
extern "C" void kernel_launch(void* const* d_in, const int* in_sizes, int n_in,
                              void* d_out, int out_size)
{
    const float* x      = (const float*)d_in[0];
    const float* W_attn = (const float*)d_in[1];
    const float* b_attn = (const float*)d_in[2];
    const float* W_proj = (const float*)d_in[3];
    const float* b_proj = (const float*)d_in[4];

    float* out   = (float*)d_out;
    float* y_out = out;
    float* m_out = out + (size_t)B_ * T_ * C_;

    float *qkv, *ff, *att;
    cudaGetSymbolAddress((void**)&qkv, g_qkv);
    cudaGetSymbolAddress((void**)&ff,  g_ff);
    cudaGetSymbolAddress((void**)&att, g_att);

    dim3 blk(256);

    // 1) QKV GEMM: tf32 bulk + exact fp32 patch for head-0 q,k columns
    sgemm_tf32<<<dim3(W3_ / 128, (B_ * T_) / 128), blk>>>(
        x, W_attn, b_attn, qkv, B_ * T_, W3_, C_);
    qk0_patch<<<dim3(2, (B_ * T_) / 64), blk>>>(x, W_attn, b_attn, qkv);

    // 2) head-0 scores (lower triangle only)
    scores_kernel<<<dim3(T_ / 64, T_ / 64, B_), blk>>>(qkv, ff);

    // 3) exclusive column cumsum (triangular, 2-pass)
    cumsum_pass1<<<dim3(T_ / 256, B_, CH_), blk>>>(ff);
    cumsum_pass2<<<dim3(T_ / 256, B_, CH_), blk>>>(ff);

    // 4) FF_sum (triangular rows)
    ffsum_kernel<<<dim3(T_, B_), blk>>>(ff);

    // 5) M output
    m_kernel<<<dim3((unsigned)(((size_t)B_ * T_ * T_) / 1024)), blk>>>(m_out);

    // 6) flash attention with penalty
    cudaFuncSetAttribute(flash_tf32,
                         cudaFuncAttributeMaxDynamicSharedMemorySize, FSMEM);
    flash_tf32<<<dim3(T_ / 128, B_ * H_), blk, FSMEM>>>(qkv, ff, att);

    // 7) output projection (tf32)
    sgemm_tf32<<<dim3(C_ / 128, (B_ * T_) / 128), blk>>>(
        att, W_proj, b_proj, y_out, B_ * T_, C_, HD_);
}

// round 6
// speedup vs baseline: 2.5127x; 1.0490x over previous
#include <cuda_runtime.h>
#include <cuda_bf16.h>
#include <cstdint>

#define B_  2
#define T_  2048
#define C_  768
#define H_  12
#define D_  64
#define HD_ 768
#define W3_ 2304   // 3*HD
#define CH_ 64
#define CL_ (T_/CH_)   // 32

typedef unsigned long long u64;

// ---- packed f32x2 helpers -------------------------------------------------
__device__ __forceinline__ u64 pk2(float lo, float hi) {
    u64 r; asm("mov.b64 %0,{%1,%2};" : "=l"(r) : "f"(lo), "f"(hi)); return r;
}
__device__ __forceinline__ u64 dup2(float v) { return pk2(v, v); }
__device__ __forceinline__ float2 up2(u64 v) {
    float2 r; asm("mov.b64 {%0,%1},%2;" : "=f"(r.x), "=f"(r.y) : "l"(v)); return r;
}
__device__ __forceinline__ void fma2(u64& d, u64 a, u64 b) {
    asm("fma.rn.f32x2 %0,%1,%2,%3;" : "=l"(d) : "l"(a), "l"(b), "l"(d));
}

// ---- tf32 helpers -----------------------------------------------------------
__device__ __forceinline__ uint32_t tf32r(float x) {
    uint32_t r; asm("cvt.rna.tf32.f32 %0,%1;" : "=r"(r) : "f"(x)); return r;
}
#define MMA_TF32(c,a,b0,b1) \
    asm volatile("mma.sync.aligned.m16n8k8.row.col.f32.tf32.tf32.f32 " \
        "{%0,%1,%2,%3},{%4,%5,%6,%7},{%8,%9},{%0,%1,%2,%3};" \
        : "+f"((c)[0]),"+f"((c)[1]),"+f"((c)[2]),"+f"((c)[3]) \
        : "r"((a)[0]),"r"((a)[1]),"r"((a)[2]),"r"((a)[3]),"r"(b0),"r"(b1))

// Scratch
__device__ float g_qkv[(size_t)B_ * T_ * W3_];
__device__ float g_ff [(size_t)B_ * T_ * T_];
__device__ float g_ffsum[B_ * T_];
__device__ float g_att[(size_t)B_ * T_ * HD_];
__device__ float g_csum[B_ * CH_ * T_];

// ---------------------------------------------------------------------------
// TF32 tensor-core GEMM with bias (unchanged from R5).
// ---------------------------------------------------------------------------
#define AST 20
#define BST 136
__global__ __launch_bounds__(256) void sgemm_tf32(
    const float* __restrict__ A, const float* __restrict__ Bm,
    const float* __restrict__ bias, float* __restrict__ Cm,
    int M, int N, int K)
{
    __shared__ float As[128 * AST];
    __shared__ float Bs[16 * BST];
    int tid = threadIdx.x, lane = tid & 31, w = tid >> 5;
    int gid = lane >> 2, tig = lane & 3;
    int row0 = blockIdx.y * 128, col0 = blockIdx.x * 128;

    int arow = tid >> 1, acol = (tid & 1) * 8;
    int brow = tid >> 4, bcol = (tid & 15) * 8;
    const float* Ap = A + (size_t)(row0 + arow) * K + acol;
    const float* Bp = Bm + (size_t)brow * N + col0 + bcol;

    float c[16][4];
#pragma unroll
    for (int g = 0; g < 16; g++)
#pragma unroll
        for (int j = 0; j < 4; j++) c[g][j] = 0.f;

    float4 a0 = *(const float4*)(Ap);
    float4 a1 = *(const float4*)(Ap + 4);
    float4 b0 = *(const float4*)(Bp);
    float4 b1 = *(const float4*)(Bp + 4);

    for (int k0 = 0; k0 < K; k0 += 16) {
        __syncthreads();
        {
            float* ad = As + arow * AST + acol;
            ad[0] = __uint_as_float(tf32r(a0.x));
            ad[1] = __uint_as_float(tf32r(a0.y));
            ad[2] = __uint_as_float(tf32r(a0.z));
            ad[3] = __uint_as_float(tf32r(a0.w));
            ad[4] = __uint_as_float(tf32r(a1.x));
            ad[5] = __uint_as_float(tf32r(a1.y));
            ad[6] = __uint_as_float(tf32r(a1.z));
            ad[7] = __uint_as_float(tf32r(a1.w));
            float* bd = Bs + brow * BST + bcol;
            bd[0] = __uint_as_float(tf32r(b0.x));
            bd[1] = __uint_as_float(tf32r(b0.y));
            bd[2] = __uint_as_float(tf32r(b0.z));
            bd[3] = __uint_as_float(tf32r(b0.w));
            bd[4] = __uint_as_float(tf32r(b1.x));
            bd[5] = __uint_as_float(tf32r(b1.y));
            bd[6] = __uint_as_float(tf32r(b1.z));
            bd[7] = __uint_as_float(tf32r(b1.w));
        }
        __syncthreads();
        if (k0 + 16 < K) {
            a0 = *(const float4*)(Ap + k0 + 16);
            a1 = *(const float4*)(Ap + k0 + 20);
            b0 = *(const float4*)(Bp + (size_t)(k0 + 16) * N);
            b1 = *(const float4*)(Bp + (size_t)(k0 + 16) * N + 4);
        }
#pragma unroll
        for (int kc = 0; kc < 2; kc++) {
            uint32_t af[4];
            const float* ab = As + (16 * w + gid) * AST + kc * 8 + tig;
            af[0] = __float_as_uint(ab[0]);
            af[1] = __float_as_uint(ab[8 * AST]);
            af[2] = __float_as_uint(ab[4]);
            af[3] = __float_as_uint(ab[8 * AST + 4]);
            const float* bb = Bs + (kc * 8 + tig) * BST + gid;
#pragma unroll
            for (int g = 0; g < 16; g++) {
                uint32_t bf0 = __float_as_uint(bb[g * 8]);
                uint32_t bf1 = __float_as_uint(bb[4 * BST + g * 8]);
                MMA_TF32(c[g], af, bf0, bf1);
            }
        }
    }

    int crow = row0 + 16 * w + gid;
#pragma unroll
    for (int g = 0; g < 16; g++) {
        int cc = col0 + g * 8 + 2 * tig;
        float bx0 = bias[cc], bx1 = bias[cc + 1];
        float2 w0 = make_float2(c[g][0] + bx0, c[g][1] + bx1);
        float2 w1 = make_float2(c[g][2] + bx0, c[g][3] + bx1);
        *(float2*)&Cm[(size_t)crow * N + cc] = w0;
        *(float2*)&Cm[(size_t)(crow + 8) * N + cc] = w1;
    }
}

// ---------------------------------------------------------------------------
// Exact fp32 patch GEMM for head-0 q,k columns (unchanged from R5).
// ---------------------------------------------------------------------------
__global__ __launch_bounds__(256) void qk0_patch(
    const float* __restrict__ x, const float* __restrict__ W,
    const float* __restrict__ bias, float* __restrict__ qkv)
{
    __shared__ float As[16][68];
    __shared__ float Bs[16][68];
    int tid = threadIdx.x;
    int tx = tid & 15, ty = tid >> 4;
    int row0 = blockIdx.y * 64;
    int colbase = blockIdx.x * 768;
    int arow = tid >> 2, acol = (tid & 3) * 4;
    int brow = tid >> 4, bcol = (tid & 15) * 4;
    const float* Ap = x + (size_t)(row0 + arow) * C_ + acol;
    const float* Bp = W + (size_t)brow * W3_ + colbase + bcol;

    u64 acc[4][2];
#pragma unroll
    for (int i = 0; i < 4; i++) { acc[i][0] = 0ull; acc[i][1] = 0ull; }

    for (int k0 = 0; k0 < C_; k0 += 16) {
        float4 a = *(const float4*)(Ap + k0);
        float4 b = *(const float4*)(Bp + (size_t)k0 * W3_);
        __syncthreads();
        As[acol + 0][arow] = a.x; As[acol + 1][arow] = a.y;
        As[acol + 2][arow] = a.z; As[acol + 3][arow] = a.w;
        *(float4*)&Bs[brow][bcol] = b;
        __syncthreads();
#pragma unroll
        for (int kk = 0; kk < 16; kk++) {
            float4 av = *(const float4*)&As[kk][ty * 4];
            u64 ad[4];
            ad[0] = dup2(av.x); ad[1] = dup2(av.y);
            ad[2] = dup2(av.z); ad[3] = dup2(av.w);
            u64 bx0 = *(const u64*)&Bs[kk][tx * 4];
            u64 bx1 = *(const u64*)&Bs[kk][tx * 4 + 2];
#pragma unroll
            for (int i = 0; i < 4; i++) {
                fma2(acc[i][0], ad[i], bx0);
                fma2(acc[i][1], ad[i], bx1);
            }
        }
    }
#pragma unroll
    for (int i = 0; i < 4; i++) {
        int r = row0 + ty * 4 + i;
        int cc = colbase + tx * 4;
        float2 p0 = up2(acc[i][0]);
        float2 p1 = up2(acc[i][1]);
        float4 o;
        o.x = p0.x + bias[cc + 0];
        o.y = p0.y + bias[cc + 1];
        o.z = p1.x + bias[cc + 2];
        o.w = p1.y + bias[cc + 3];
        *(float4*)&qkv[(size_t)r * W3_ + cc] = o;
    }
}

// ---------------------------------------------------------------------------
// Head-0 selection scores (unchanged from R5).
// ---------------------------------------------------------------------------
__global__ __launch_bounds__(256) void scores_kernel(
    const float* __restrict__ qkv, float* __restrict__ S)
{
    int b = blockIdx.z, tb = blockIdx.y, sb = blockIdx.x;
    int t0 = tb * 64, s0 = sb * 64;
    if (s0 > t0) return;
    int tid = threadIdx.x, tx = tid & 15, ty = tid >> 4;
    float* Sb = S + (size_t)b * T_ * T_;

    __shared__ float Qs[64][68];
    __shared__ float Ks[64][68];
    const float* qb = qkv + ((size_t)b * T_ + t0) * W3_;
    const float* kb = qkv + ((size_t)b * T_ + s0) * W3_ + HD_;
    int lr = tid >> 4, lc = (tid & 15) * 4;
#pragma unroll
    for (int g = 0; g < 4; g++) {
        int r = lr + g * 16;
        *(float4*)&Qs[r][lc] = *(const float4*)&qb[(size_t)r * W3_ + lc];
        *(float4*)&Ks[r][lc] = *(const float4*)&kb[(size_t)r * W3_ + lc];
    }
    __syncthreads();

    float acc[4][4] = {};
#pragma unroll
    for (int dk = 0; dk < 16; dk++) {
        float4 qv[4], kv[4];
#pragma unroll
        for (int i = 0; i < 4; i++) qv[i] = *(const float4*)&Qs[ty * 4 + i][dk * 4];
#pragma unroll
        for (int j = 0; j < 4; j++) kv[j] = *(const float4*)&Ks[tx * 4 + j][dk * 4];
#pragma unroll
        for (int i = 0; i < 4; i++)
#pragma unroll
            for (int j = 0; j < 4; j++)
                acc[i][j] += qv[i].x * kv[j].x + qv[i].y * kv[j].y
                           + qv[i].z * kv[j].z + qv[i].w * kv[j].w;
    }
#pragma unroll
    for (int i = 0; i < 4; i++) {
        int t = t0 + ty * 4 + i;
        float out[4];
#pragma unroll
        for (int j = 0; j < 4; j++) {
            int s = s0 + tx * 4 + j;
            float v = acc[i][j] * 0.125f;
            out[j] = (s < t && s > 0) ? fmaxf(v, 0.f) : 0.f;
        }
        *(float4*)&Sb[(size_t)t * T_ + s0 + tx * 4] = *(float4*)out;
    }
}

// ---------------------------------------------------------------------------
// Two-pass exclusive column cumsum (unchanged from R5).
// ---------------------------------------------------------------------------
__global__ __launch_bounds__(256) void cumsum_pass1(const float* __restrict__ S)
{
    int b = blockIdx.y, chunk = blockIdx.z;
    int c0 = chunk * CL_;
    int s0 = blockIdx.x * 256;
    int s = s0 + threadIdx.x;
    float* dst = &g_csum[(b * CH_ + chunk) * T_ + s];
    if (s0 >= c0 + CL_ - 1) { *dst = 0.f; return; }
    const float* p = S + (size_t)b * T_ * T_ + (size_t)c0 * T_ + s;
    float acc = 0.f;
#pragma unroll 8
    for (int t = 0; t < CL_; t++) {
        float v = p[(size_t)t * T_];
        acc += (c0 + t > s) ? v : 0.f;
    }
    *dst = acc;
}

__global__ __launch_bounds__(256) void cumsum_pass2(float* __restrict__ S)
{
    int b = blockIdx.y, chunk = blockIdx.z;
    int c0 = chunk * CL_;
    int s0 = blockIdx.x * 256;
    if (s0 >= c0 + CL_) return;
    int s = s0 + threadIdx.x;
    float base = 0.f;
    for (int c = 0; c < chunk; c++) base += g_csum[(b * CH_ + c) * T_ + s];
    float* p = S + (size_t)b * T_ * T_ + (size_t)c0 * T_ + s;
    float acc = base;
#pragma unroll 8
    for (int t = 0; t < CL_; t++) {
        float v = p[(size_t)t * T_];
        p[(size_t)t * T_] = acc;
        acc += (c0 + t > s) ? v : 0.f;
    }
}

// ---------------------------------------------------------------------------
__global__ __launch_bounds__(256) void ffsum_kernel(const float* __restrict__ FF)
{
    int b = blockIdx.y, t = blockIdx.x;
    const float4* row = (const float4*)(FF + ((size_t)b * T_ + t) * T_);
    int n4 = (t >> 2) + 1;
    float s = 0.f;
    for (int j = threadIdx.x; j < n4; j += 256) {
        float4 v = row[j];
        int sb = j * 4;
        s += (sb     <= t ? fminf(v.x, 1.f) : 0.f)
           + (sb + 1 <= t ? fminf(v.y, 1.f) : 0.f)
           + (sb + 2 <= t ? fminf(v.z, 1.f) : 0.f)
           + (sb + 3 <= t ? fminf(v.w, 1.f) : 0.f);
    }
#pragma unroll
    for (int off = 16; off; off >>= 1) s += __shfl_xor_sync(0xffffffffu, s, off);
    __shared__ float red[8];
    int lane = threadIdx.x & 31, w = threadIdx.x >> 5;
    if (lane == 0) red[w] = s;
    __syncthreads();
    if (w == 0) {
        s = (lane < 8) ? red[lane] : 0.f;
#pragma unroll
        for (int off = 4; off; off >>= 1) s += __shfl_xor_sync(0xffffffffu, s, off);
        if (lane == 0) g_ffsum[b * T_ + t] = s;
    }
}

__global__ __launch_bounds__(256) void m_kernel(float* __restrict__ Mout)
{
    size_t idx4 = (size_t)blockIdx.x * 256 + threadIdx.x;
    size_t idx = idx4 * 4;
    int j = (int)(idx % T_);
    size_t r = idx / T_;
    int i = (int)(r % T_);
    int b = (int)(r / T_);
    float4 fs = *(const float4*)&g_ffsum[b * T_ + j];
    float fi = (float)i;
    float4 o = make_float4(fi - fs.x, fi - fs.y, fi - fs.z, fi - fs.w);
    *(float4*)&Mout[idx] = o;
}

// ---------------------------------------------------------------------------
// Flash attention v2 — TF32 mma, m=32/warp (2x B-frag reuse), s-tile 64,
// P passed QK->PV via register shuffles (no P smem). 128 threads (4 warps),
// each warp owns 32 q-rows (two m16 tiles). 2 blocks/SM.
// ---------------------------------------------------------------------------
#define FSTQ 68
#define FSTV 72
#define QOF 0
#define KOF (128 * FSTQ)
#define VOF (KOF + 64 * FSTQ)
#define FSMEM ((128 * FSTQ + 64 * FSTQ + 64 * FSTV) * 4)   // 70656 B
#define L2E 1.44269504f

__device__ __forceinline__ uint4 cvt4(float4 v) {
    uint4 r;
    r.x = tf32r(v.x); r.y = tf32r(v.y); r.z = tf32r(v.z); r.w = tf32r(v.w);
    return r;
}

__global__ __launch_bounds__(128) void flash_tf32(
    const float* __restrict__ qkv, const float* __restrict__ FF,
    float* __restrict__ Y)
{
    extern __shared__ __align__(16) float sm[];

    int tid = threadIdx.x;
    int lane = tid & 31, w = tid >> 5;          // 4 warps
    int gid = lane >> 2, tig = lane & 3;
    int tb = gridDim.x - 1 - blockIdx.x;        // big tiles first
    int bh = blockIdx.y;
    int b = bh / H_, h = bh % H_;
    int t0 = tb * 128;

    const float* kvb = qkv + (size_t)b * T_ * W3_;

    // ---- load Q tile (128 rows x 64) -> tf32 smem, one row per thread ----
    {
        const float* qp = kvb + (size_t)(t0 + tid) * W3_ + h * D_;
        uint4* dst = (uint4*)(sm + QOF + tid * FSTQ);
#pragma unroll
        for (int u = 0; u < 16; u++)
            dst[u] = cvt4(*(const float4*)(qp + u * 4));
    }
    __syncthreads();

    // ---- Q A-fragments: 2 m-tiles x 8 k-chunks ----
    uint32_t aq[2][8][4];
#pragma unroll
    for (int mt = 0; mt < 2; mt++)
#pragma unroll
        for (int kc = 0; kc < 8; kc++) {
            const float* q0 = sm + QOF + (32 * w + 16 * mt + gid) * FSTQ + kc * 8 + tig;
            aq[mt][kc][0] = __float_as_uint(q0[0]);
            aq[mt][kc][1] = __float_as_uint(q0[8 * FSTQ]);
            aq[mt][kc][2] = __float_as_uint(q0[4]);
            aq[mt][kc][3] = __float_as_uint(q0[8 * FSTQ + 4]);
        }

    float mrow[2][2], lrow[2][2];
    float o[2][8][4];
#pragma unroll
    for (int mt = 0; mt < 2; mt++) {
        mrow[mt][0] = -1e30f; mrow[mt][1] = -1e30f;
        lrow[mt][0] = 0.f;    lrow[mt][1] = 0.f;
#pragma unroll
        for (int dg = 0; dg < 8; dg++)
#pragma unroll
            for (int j = 0; j < 4; j++) o[mt][dg][j] = 0.f;
    }

    int qr[2] = { t0 + 32 * w + gid, t0 + 32 * w + 16 + gid };
    const float* ffb = FF + (size_t)b * T_ * T_;
    int cl = tig << 1;
    int src0 = (lane & ~3) | (tig >> 1);
    int src1 = src0 + 2;
    bool od = (tig & 1);

    int nkb = 2 * tb + 2;
    for (int kb = 0; kb < nkb; kb++) {
        int s0 = kb * 64;
        __syncthreads();
        // ---- load K,V tiles (64 x 64 each), half row per thread ----
        {
            int r = tid >> 1, c0 = (tid & 1) * 32;
            const float* kp = kvb + (size_t)(s0 + r) * W3_ + HD_     + h * D_ + c0;
            const float* vp = kvb + (size_t)(s0 + r) * W3_ + 2 * HD_ + h * D_ + c0;
            uint4* dk = (uint4*)(sm + KOF + r * FSTQ + c0);
            uint4* dv = (uint4*)(sm + VOF + r * FSTV + c0);
#pragma unroll
            for (int u = 0; u < 8; u++) {
                dk[u] = cvt4(*(const float4*)(kp + u * 4));
                dv[u] = cvt4(*(const float4*)(vp + u * 4));
            }
        }
        __syncthreads();

        // ---- QK^T: 2 m-tiles x 8 n8-tiles, B-frag shared across m-tiles ----
        float acc[2][8][4];
#pragma unroll
        for (int mt = 0; mt < 2; mt++)
#pragma unroll
            for (int g = 0; g < 8; g++)
#pragma unroll
                for (int j = 0; j < 4; j++) acc[mt][g][j] = 0.f;

#pragma unroll
        for (int kc = 0; kc < 8; kc++) {
#pragma unroll
            for (int g = 0; g < 8; g++) {
                const float* kpK = sm + KOF + (g * 8 + gid) * FSTQ + kc * 8 + tig;
                uint32_t b0 = __float_as_uint(kpK[0]);
                uint32_t b1 = __float_as_uint(kpK[4]);
                MMA_TF32(acc[0][g], aq[0][kc], b0, b1);
                MMA_TF32(acc[1][g], aq[1][kc], b0, b1);
            }
        }

        // ---- logits (log2 domain), FF subtract, causal mask, softmax ----
        bool diag = (kb >= nkb - 2);
#pragma unroll
        for (int mt = 0; mt < 2; mt++) {
            const float* f0 = ffb + (size_t)qr[mt] * T_;
            const float* f1 = f0 + 8 * T_;
#pragma unroll
            for (int g = 0; g < 8; g++) {
                int sc = s0 + 8 * g + cl;
                float2 fa = *(const float2*)(f0 + sc);
                float2 fb = *(const float2*)(f1 + sc);
                acc[mt][g][0] = acc[mt][g][0] * (0.125f * L2E) - fa.x * L2E;
                acc[mt][g][1] = acc[mt][g][1] * (0.125f * L2E) - fa.y * L2E;
                acc[mt][g][2] = acc[mt][g][2] * (0.125f * L2E) - fb.x * L2E;
                acc[mt][g][3] = acc[mt][g][3] * (0.125f * L2E) - fb.y * L2E;
                if (diag) {
                    if (sc     > qr[mt])     acc[mt][g][0] = -1e30f;
                    if (sc + 1 > qr[mt])     acc[mt][g][1] = -1e30f;
                    if (sc     > qr[mt] + 8) acc[mt][g][2] = -1e30f;
                    if (sc + 1 > qr[mt] + 8) acc[mt][g][3] = -1e30f;
                }
            }
            float mx0 = -1e30f, mx1 = -1e30f;
#pragma unroll
            for (int g = 0; g < 8; g++) {
                mx0 = fmaxf(mx0, fmaxf(acc[mt][g][0], acc[mt][g][1]));
                mx1 = fmaxf(mx1, fmaxf(acc[mt][g][2], acc[mt][g][3]));
            }
            mx0 = fmaxf(mx0, __shfl_xor_sync(0xffffffffu, mx0, 1));
            mx0 = fmaxf(mx0, __shfl_xor_sync(0xffffffffu, mx0, 2));
            mx1 = fmaxf(mx1, __shfl_xor_sync(0xffffffffu, mx1, 1));
            mx1 = fmaxf(mx1, __shfl_xor_sync(0xffffffffu, mx1, 2));
            float mn0 = fmaxf(mrow[mt][0], mx0), mn1 = fmaxf(mrow[mt][1], mx1);
            float c0 = exp2f(mrow[mt][0] - mn0), c1 = exp2f(mrow[mt][1] - mn1);
            mrow[mt][0] = mn0; mrow[mt][1] = mn1;

            float s0r = 0.f, s1r = 0.f;
#pragma unroll
            for (int g = 0; g < 8; g++) {
                acc[mt][g][0] = exp2f(acc[mt][g][0] - mn0);
                acc[mt][g][1] = exp2f(acc[mt][g][1] - mn0);
                acc[mt][g][2] = exp2f(acc[mt][g][2] - mn1);
                acc[mt][g][3] = exp2f(acc[mt][g][3] - mn1);
                s0r += acc[mt][g][0] + acc[mt][g][1];
                s1r += acc[mt][g][2] + acc[mt][g][3];
            }
            s0r += __shfl_xor_sync(0xffffffffu, s0r, 1);
            s0r += __shfl_xor_sync(0xffffffffu, s0r, 2);
            s1r += __shfl_xor_sync(0xffffffffu, s1r, 1);
            s1r += __shfl_xor_sync(0xffffffffu, s1r, 2);
            lrow[mt][0] = lrow[mt][0] * c0 + s0r;
            lrow[mt][1] = lrow[mt][1] * c1 + s1r;
#pragma unroll
            for (int dg = 0; dg < 8; dg++) {
                o[mt][dg][0] *= c0; o[mt][dg][1] *= c0;
                o[mt][dg][2] *= c1; o[mt][dg][3] *= c1;
            }
        }

        // ---- PV: P fragments via warp shuffles, V B-frags shared by m-tiles ----
#pragma unroll
        for (int kc = 0; kc < 8; kc++) {
            uint32_t ap0[4], ap1[4];
            {
                float x0 = __shfl_sync(0xffffffffu, acc[0][kc][0], src0);
                float x1 = __shfl_sync(0xffffffffu, acc[0][kc][1], src0);
                float y0 = __shfl_sync(0xffffffffu, acc[0][kc][0], src1);
                float y1 = __shfl_sync(0xffffffffu, acc[0][kc][1], src1);
                float z0 = __shfl_sync(0xffffffffu, acc[0][kc][2], src0);
                float z1 = __shfl_sync(0xffffffffu, acc[0][kc][3], src0);
                float u0 = __shfl_sync(0xffffffffu, acc[0][kc][2], src1);
                float u1 = __shfl_sync(0xffffffffu, acc[0][kc][3], src1);
                ap0[0] = tf32r(od ? x1 : x0);
                ap0[1] = tf32r(od ? z1 : z0);
                ap0[2] = tf32r(od ? y1 : y0);
                ap0[3] = tf32r(od ? u1 : u0);
            }
            {
                float x0 = __shfl_sync(0xffffffffu, acc[1][kc][0], src0);
                float x1 = __shfl_sync(0xffffffffu, acc[1][kc][1], src0);
                float y0 = __shfl_sync(0xffffffffu, acc[1][kc][0], src1);
                float y1 = __shfl_sync(0xffffffffu, acc[1][kc][1], src1);
                float z0 = __shfl_sync(0xffffffffu, acc[1][kc][2], src0);
                float z1 = __shfl_sync(0xffffffffu, acc[1][kc][3], src0);
                float u0 = __shfl_sync(0xffffffffu, acc[1][kc][2], src1);
                float u1 = __shfl_sync(0xffffffffu, acc[1][kc][3], src1);
                ap1[0] = tf32r(od ? x1 : x0);
                ap1[1] = tf32r(od ? z1 : z0);
                ap1[2] = tf32r(od ? y1 : y0);
                ap1[3] = tf32r(od ? u1 : u0);
            }
#pragma unroll
            for (int dg = 0; dg < 8; dg++) {
                const float* vr = sm + VOF + (kc * 8 + tig) * FSTV + dg * 8 + gid;
                uint32_t b0 = __float_as_uint(vr[0]);
                uint32_t b1 = __float_as_uint(vr[4 * FSTV]);
                MMA_TF32(o[0][dg], ap0, b0, b1);
                MMA_TF32(o[1][dg], ap1, b0, b1);
            }
        }
    }

    // ---- write y ----
#pragma unroll
    for (int mt = 0; mt < 2; mt++) {
        float i0 = 1.f / lrow[mt][0], i1 = 1.f / lrow[mt][1];
        float* yb = Y + (size_t)(b * T_ + qr[mt]) * HD_ + h * D_;
#pragma unroll
        for (int dg = 0; dg < 8; dg++) {
            int dc = 8 * dg + cl;
            float2 w0 = make_float2(o[mt][dg][0] * i0, o[mt][dg][1] * i0);
            float2 w1 = make_float2(o[mt][dg][2] * i1, o[mt][dg][3] * i1);
            *(float2*)(yb + dc) = w0;
            *(float2*)(yb + 8 * (size_t)HD_ + dc) = w1;
        }
    }
}

// ---------------------------------------------------------------------------
extern "C" void kernel_launch(void* const* d_in, const int* in_sizes, int n_in,
                              void* d_out, int out_size)
{
    const float* x      = (const float*)d_in[0];
    const float* W_attn = (const float*)d_in[1];
    const float* b_attn = (const float*)d_in[2];
    const float* W_proj = (const float*)d_in[3];
    const float* b_proj = (const float*)d_in[4];

    float* out   = (float*)d_out;
    float* y_out = out;
    float* m_out = out + (size_t)B_ * T_ * C_;

    float *qkv, *ff, *att;
    cudaGetSymbolAddress((void**)&qkv, g_qkv);
    cudaGetSymbolAddress((void**)&ff,  g_ff);
    cudaGetSymbolAddress((void**)&att, g_att);

    dim3 blk(256);

    sgemm_tf32<<<dim3(W3_ / 128, (B_ * T_) / 128), blk>>>(
        x, W_attn, b_attn, qkv, B_ * T_, W3_, C_);
    qk0_patch<<<dim3(2, (B_ * T_) / 64), blk>>>(x, W_attn, b_attn, qkv);

    scores_kernel<<<dim3(T_ / 64, T_ / 64, B_), blk>>>(qkv, ff);

    cumsum_pass1<<<dim3(T_ / 256, B_, CH_), blk>>>(ff);
    cumsum_pass2<<<dim3(T_ / 256, B_, CH_), blk>>>(ff);

    ffsum_kernel<<<dim3(T_, B_), blk>>>(ff);

    m_kernel<<<dim3((unsigned)(((size_t)B_ * T_ * T_) / 1024)), blk>>>(m_out);

    cudaFuncSetAttribute(flash_tf32,
                         cudaFuncAttributeMaxDynamicSharedMemorySize, FSMEM);
    flash_tf32<<<dim3(T_ / 128, B_ * H_), dim3(128), FSMEM>>>(qkv, ff, att);

    sgemm_tf32<<<dim3(C_ / 128, (B_ * T_) / 128), blk>>>(
        att, W_proj, b_proj, y_out, B_ * T_, C_, HD_);
}